// round 12
// baseline (speedup 1.0000x reference)
#include <cuda_runtime.h>
#include <cuda_fp16.h>
#include <math.h>
#include <stdint.h>

#define B_  4
#define L_  1024
#define D_  1024
#define H_  16
#define HD_ 64
#define M_TOT (B_*L_)   // 4096

// ---------------------------------------------------------------------------
// Scratch
// ---------------------------------------------------------------------------
__device__ float g_x[M_TOT * D_];
__device__ float4 g_prep[B_ * H_ * L_];     // (sc, sin, cos, 0) per (bh,l)
__device__ __half g_ahi[M_TOT * D_];        // activations / ctx fp16
__device__ __half g_w16[4 * D_ * D_];       // W fp16, [K][N] layout (q,k,v,o)
__device__ __half g_qhi[M_TOT * D_];        // rotated Q fp16, head-major
__device__ __half g_khi[M_TOT * D_];        // rotated K fp16, head-major
__device__ __half g_vhi[M_TOT * D_];        // V fp16, head-major

// ---------------------------------------------------------------------------
// Helpers
// ---------------------------------------------------------------------------
__device__ __forceinline__ uint32_t smem_to_u32(const void* p) {
    uint32_t a;
    asm("{ .reg .u64 t; cvta.to.shared.u64 t, %1; cvt.u32.u64 %0, t; }"
        : "=r"(a) : "l"(p));
    return a;
}

#define CP16(dst, src) \
    asm volatile("cp.async.cg.shared.global [%0], [%1], 16;" \
                 :: "r"(dst), "l"(src) : "memory")
#define CP_COMMIT() asm volatile("cp.async.commit_group;" ::: "memory")
#define CP_WAIT(n)  asm volatile("cp.async.wait_group %0;" :: "n"(n) : "memory")

#define LDSM4(r, addr) \
    asm volatile("ldmatrix.sync.aligned.m8n8.x4.shared.b16 {%0,%1,%2,%3}, [%4];" \
                 : "=r"((r)[0]), "=r"((r)[1]), "=r"((r)[2]), "=r"((r)[3]) : "r"(addr))
#define LDSM4T(r, addr) \
    asm volatile("ldmatrix.sync.aligned.m8n8.x4.trans.shared.b16 {%0,%1,%2,%3}, [%4];" \
                 : "=r"((r)[0]), "=r"((r)[1]), "=r"((r)[2]), "=r"((r)[3]) : "r"(addr))

#define MMA16816(c, a, b0, b1) \
    asm volatile("mma.sync.aligned.m16n8k16.row.col.f32.f16.f16.f32 " \
                 "{%0,%1,%2,%3}, {%4,%5,%6,%7}, {%8,%9}, {%0,%1,%2,%3};" \
                 : "+f"((c)[0]), "+f"((c)[1]), "+f"((c)[2]), "+f"((c)[3]) \
                 : "r"((a)[0]), "r"((a)[1]), "r"((a)[2]), "r"((a)[3]), \
                   "r"(b0), "r"(b1))

// pack two floats -> fp16x2 (x in low half)
__device__ __forceinline__ uint32_t pack2h(float x, float y) {
    uint32_t d;
    asm("cvt.rn.f16x2.f32 %0, %1, %2;" : "=r"(d) : "f"(y), "f"(x));
    return d;
}

// ---------------------------------------------------------------------------
// prelude (fused): z=0 convA (hidden fp32->fp16), z=1 convW stream
// (4x W fp32->fp16 same [K][N] layout), z=2 prep (scale/sin/cos).
// ---------------------------------------------------------------------------
__global__ __launch_bounds__(256) void prelude(
    const float4* __restrict__ hidden,
    const float4* __restrict__ Wq, const float4* __restrict__ Wk,
    const float4* __restrict__ Wv, const float4* __restrict__ Wo,
    const float* __restrict__ phi, const float* __restrict__ mag,
    const float* __restrict__ gamma,
    uint2* __restrict__ ahi, uint2* __restrict__ w16,
    float4* __restrict__ prp)
{
    const int z = blockIdx.z;
    int i = blockIdx.x * 256 + threadIdx.x;
    if (z == 0) {
        // convA: 1048576 float4s
        float4 v = hidden[i];
        uint2 ho;
        ho.x = pack2h(v.x, v.y);
        ho.y = pack2h(v.z, v.w);
        ahi[i] = ho;
    } else if (z == 1) {
        // convW: 4 matrices x 262144 float4 each (2^18)
        int w = i >> 18, off = i & 262143;
        const float4* W = (w == 0) ? Wq : (w == 1) ? Wk : (w == 2) ? Wv : Wo;
        float4 v = W[off];
        uint2 ho;
        ho.x = pack2h(v.x, v.y);
        ho.y = pack2h(v.z, v.w);
        w16[i] = ho;
    } else {
        if (i >= B_ * H_ * L_) return;
        int h = (i >> 10) & 15;
        float sc = 1.0f + gamma[h] * tanhf(mag[i]);
        float s, c;
        sincosf(phi[i], &s, &c);
        prp[i] = make_float4(sc, s, c, 0.f);
    }
}

// ---------------------------------------------------------------------------
// HMMA fp16 GEMM, 128x128 CTA tile, 256 threads = 8 warps (32x64 tiles),
// 3-stage cp.async pipeline, 2 CTAs/SM. B kept in [K][N] layout, fragments
// via ldmatrix.trans (same pattern as the attention V path).
// Modes:
//  res == nullptr, z=0/1: Q/K -> bias+scale+rotate -> fp16 head-major
//  res == nullptr, z=2:   V  -> bias -> fp16 head-major
//  res != nullptr:        Wo -> bias + residual -> fp32 row-major
// ---------------------------------------------------------------------------
#define GM 128
#define GN 128
#define KC 64
#define OFF_BHI  16384
#define STAGE    32768
#define NSTG     3
#define GEMM_DYN (NSTG*STAGE)   // 98304

__global__ __launch_bounds__(256, 2) void gemm_hmma(
    const __half* __restrict__ Ahi,
    const __half* __restrict__ W16,
    const float* __restrict__ bias0, const float* __restrict__ bias1,
    const float* __restrict__ bias2,
    const float4* __restrict__ prp,
    __half* __restrict__ qh, __half* __restrict__ kh,
    __half* __restrict__ vh,
    const float* __restrict__ res, float* __restrict__ xout)
{
    extern __shared__ char smraw[];
    const uint32_t sbase = smem_to_u32(smraw);
    const int tid  = threadIdx.x;
    const int lane = tid & 31, wid = tid >> 5;
    const int wm = wid >> 1, wn = wid & 1;    // 4 x 2 warps of 32x64
    const int bm = blockIdx.y * GM, bn = blockIdx.x * GN;
    const int z  = blockIdx.z;

    const __half* Bw = W16 + (size_t)z * D_ * D_;   // [K][N]
    const float* bias = (z == 0) ? bias0 : (z == 1) ? bias1 : bias2;

    // A loader indices: 128 rows x 8 segs (128B rows)
    const int rrA  = tid >> 3;     // 0..31
    const int segA = tid & 7;
    // B loader indices: 64 rows x 16 segs (256B rows, two 128B halves)
    const int rB_  = tid >> 4;     // 0..15
    const int segB = tid & 15;

    #define LOAD_STAGE(s, kc) do { \
        uint32_t sb_ = sbase + (uint32_t)(s) * STAGE; \
        _Pragma("unroll") \
        for (int h4 = 0; h4 < 4; h4++) { \
            int r_ = rrA + h4 * 32; \
            uint32_t sw_ = (uint32_t)r_ * 128 + (uint32_t)((segA ^ (r_ & 7)) << 4); \
            size_t ga_ = (size_t)(bm + r_) * D_ + (kc) + segA * 8; \
            CP16(sb_ + sw_, Ahi + ga_); \
        } \
        _Pragma("unroll") \
        for (int h4 = 0; h4 < 4; h4++) { \
            int r_ = rB_ + h4 * 16; \
            uint32_t sw_ = (uint32_t)r_ * 256 + (uint32_t)((segB >> 3) << 7) \
                         + (uint32_t)(((segB & 7) ^ (r_ & 7)) << 4); \
            size_t gb_ = (size_t)((kc) + r_) * D_ + bn + segB * 8; \
            CP16(sb_ + OFF_BHI + sw_, Bw + gb_); \
        } \
        CP_COMMIT(); \
    } while (0)

    float c[2][8][4];
    #pragma unroll
    for (int mi = 0; mi < 2; mi++)
        #pragma unroll
        for (int ni = 0; ni < 8; ni++)
            #pragma unroll
            for (int e = 0; e < 4; e++) c[mi][ni][e] = 0.f;

    LOAD_STAGE(0, 0);
    LOAD_STAGE(1, KC);

    const int rAb = wm * 32 + (lane & 15);
    const int sgA = lane >> 4;

    int cur = 0;
    for (int ch = 0; ch < 16; ch++) {
        if (ch < 15) CP_WAIT(1);
        else         CP_WAIT(0);
        __syncthreads();
        if (ch < 14) {
            int nxt = cur + 2;
            if (nxt >= 3) nxt -= 3;
            LOAD_STAGE(nxt, (ch + 2) * KC);
        }

        const uint32_t sb = sbase + (uint32_t)cur * STAGE;
        #pragma unroll
        for (int ks = 0; ks < 4; ks++) {
            uint32_t ah[2][4];
            #pragma unroll
            for (int mi = 0; mi < 2; mi++) {
                int rA = rAb + mi * 16;
                uint32_t addr = sb + (uint32_t)rA * 128
                              + (uint32_t)(((ks * 2 + sgA) ^ (rA & 7)) << 4);
                LDSM4(ah[mi], addr);
            }
            // B fragments: rows = k, ldmatrix.trans (attention-V pattern)
            int rB = ks * 16 + (lane & 15);
            uint32_t rowb = sb + OFF_BHI + (uint32_t)rB * 256;
            #pragma unroll
            for (int np = 0; np < 4; np++) {
                int cs = wn * 8 + np * 2 + (lane >> 4);   // 16B col-segment
                uint32_t addr = rowb + (uint32_t)((cs >> 3) << 7)
                              + (uint32_t)(((cs & 7) ^ (rB & 7)) << 4);
                uint32_t bh[4];
                LDSM4T(bh, addr);
                #pragma unroll
                for (int hf = 0; hf < 2; hf++) {
                    int ni = np * 2 + hf, rb = hf * 2;
                    #pragma unroll
                    for (int mi = 0; mi < 2; mi++)
                        MMA16816(c[mi][ni], ah[mi], bh[rb], bh[rb + 1]);
                }
            }
        }
        cur++;
        if (cur == 3) cur = 0;
    }

    // ---- epilogue ----
    const int g = lane >> 2, tig = lane & 3;
    if (res) {
        // Wo projection + bias + residual -> fp32 row-major
        #pragma unroll
        for (int mi = 0; mi < 2; mi++) {
            int row0 = bm + wm * 32 + mi * 16 + g;
            #pragma unroll
            for (int ni = 0; ni < 8; ni++) {
                int col = bn + wn * 64 + ni * 8 + tig * 2;
                float2 bv = *(const float2*)(bias + col);
                float2 r0 = *(const float2*)(res + (size_t)row0 * D_ + col);
                float2 r1 = *(const float2*)(res + (size_t)(row0 + 8) * D_ + col);
                *(float2*)(xout + (size_t)row0 * D_ + col) =
                    make_float2(c[mi][ni][0] + bv.x + r0.x, c[mi][ni][1] + bv.y + r0.y);
                *(float2*)(xout + (size_t)(row0 + 8) * D_ + col) =
                    make_float2(c[mi][ni][2] + bv.x + r1.x, c[mi][ni][3] + bv.y + r1.y);
            }
        }
    } else if (z == 2) {
        // V: bias -> fp16 head-major
        #pragma unroll
        for (int mi = 0; mi < 2; mi++) {
            int row0 = bm + wm * 32 + mi * 16 + g;
            int bidx = row0 >> 10, l0 = row0 & 1023;
            #pragma unroll
            for (int ni = 0; ni < 8; ni++) {
                int col = bn + wn * 64 + ni * 8 + tig * 2;
                float2 bv = *(const float2*)(bias + col);
                size_t o0 = (((size_t)bidx * 16 + (col >> 6)) * 1024 + l0) * 64 + (col & 63);
                size_t o1 = o0 + 8 * 64;
                *(uint32_t*)(vh + o0) = pack2h(c[mi][ni][0] + bv.x, c[mi][ni][1] + bv.y);
                *(uint32_t*)(vh + o1) = pack2h(c[mi][ni][2] + bv.x, c[mi][ni][3] + bv.y);
            }
        }
    } else {
        // Q/K: bias + scale + rotate -> fp16 head-major
        __half* oh = (z == 0) ? qh : kh;
        const int hh = (bn + wn * 64) >> 6;
        #pragma unroll
        for (int mi = 0; mi < 2; mi++) {
            int row0 = bm + wm * 32 + mi * 16 + g;
            int bidx = row0 >> 10, l0 = row0 & 1023;
            int pidx = (bidx * 16 + hh) * 1024 + l0;
            float4 p0 = prp[pidx];
            float4 p1 = prp[pidx + 8];
            size_t ob = ((size_t)(bidx * 16 + hh) * 1024 + l0) * 64;
            #pragma unroll
            for (int ni = 0; ni < 4; ni++) {
                int d = ni * 8 + tig * 2;
                float2 b1 = *(const float2*)(bias + bn + wn * 64 + d);
                float2 b2 = *(const float2*)(bias + bn + wn * 64 + d + 32);
                // row0
                {
                    float x0 = (c[mi][ni][0]   + b1.x) * p0.x;
                    float x1 = (c[mi][ni][1]   + b1.y) * p0.x;
                    float y0 = (c[mi][ni+4][0] + b2.x) * p0.x;
                    float y1 = (c[mi][ni+4][1] + b2.y) * p0.x;
                    *(uint32_t*)(oh + ob + d) =
                        pack2h(x0 * p0.z - y0 * p0.y, x1 * p0.z - y1 * p0.y);
                    *(uint32_t*)(oh + ob + d + 32) =
                        pack2h(y0 * p0.z + x0 * p0.y, y1 * p0.z + x1 * p0.y);
                }
                // row0 + 8
                {
                    float x0 = (c[mi][ni][2]   + b1.x) * p1.x;
                    float x1 = (c[mi][ni][3]   + b1.y) * p1.x;
                    float y0 = (c[mi][ni+4][2] + b2.x) * p1.x;
                    float y1 = (c[mi][ni+4][3] + b2.y) * p1.x;
                    *(uint32_t*)(oh + ob + 512 + d) =
                        pack2h(x0 * p1.z - y0 * p1.y, x1 * p1.z - y1 * p1.y);
                    *(uint32_t*)(oh + ob + 512 + d + 32) =
                        pack2h(y0 * p1.z + x0 * p1.y, y1 * p1.z + x1 * p1.y);
                }
            }
        }
    }
    #undef LOAD_STAGE
}

// ---------------------------------------------------------------------------
// HMMA fp16 flash attention, 1-term, 3-stage KV pipeline (unchanged).
// ---------------------------------------------------------------------------
#define AT_Q   0
#define AT_STG 16384
#define KVSTG  16384                  // K @0, V @8192
#define AT_MASK (AT_STG + 3*KVSTG)    // 65536
#define ATTN_DYN (AT_MASK + 4096)     // 69632

__global__ __launch_bounds__(256, 2) void attn_hmma(
    const __half* __restrict__ qhi,
    const __half* __restrict__ khi,
    const __half* __restrict__ vhi,
    const float* __restrict__ mask,
    __half* __restrict__ chi)
{
    extern __shared__ char smraw[];
    const uint32_t sb = smem_to_u32(smraw);
    const int tid = threadIdx.x, lane = tid & 31, w = tid >> 5;
    const int qt = blockIdx.x, bh = blockIdx.y;
    const int b = bh >> 4, h = bh & 15;

    CP16(sb + AT_MASK + tid * 16, mask + b * 1024 + tid * 4);
    #pragma unroll
    for (int it = 0; it < 4; it++) {
        int idx = tid + it * 256, r = idx >> 3, seg = idx & 7;
        size_t g = ((size_t)bh * 1024 + qt * 128 + r) * 64 + seg * 8;
        uint32_t d = sb + (uint32_t)r * 128 + (uint32_t)((seg ^ (r & 7)) << 4);
        CP16(d + AT_Q, qhi + g);
    }
    CP_COMMIT();

    #define LOADKV(s, kt_) do { \
        _Pragma("unroll") \
        for (int it = 0; it < 2; it++) { \
            int idx = tid + it * 256, r = idx >> 3, sg = idx & 7; \
            size_t g = ((size_t)bh * 1024 + (kt_) * 64 + r) * 64 + sg * 8; \
            uint32_t d = sb + AT_STG + (uint32_t)(s) * KVSTG \
                       + (uint32_t)r * 128 + (uint32_t)((sg ^ (r & 7)) << 4); \
            CP16(d,        khi + g); \
            CP16(d + 8192, vhi + g); \
        } \
        CP_COMMIT(); \
    } while (0)

    LOADKV(0, 0);
    LOADKV(1, 1);

    float o[8][4];
    #pragma unroll
    for (int j = 0; j < 8; j++)
        #pragma unroll
        for (int e = 0; e < 4; e++) o[j][e] = 0.f;
    float m0 = -INFINITY, m1 = -INFINITY, l0 = 0.f, l1 = 0.f;

    const int rA = w * 16 + (lane & 15);
    const int rBb = ((lane >> 4) << 3) + (lane & 7);
    const int c2 = (lane & 3) * 2;

    int cur = 0;
    for (int kt = 0; kt < 16; kt++) {
        if (kt < 15) CP_WAIT(1);
        else         CP_WAIT(0);
        __syncthreads();
        if (kt < 14) {
            int nxt = cur + 2;
            if (nxt >= 3) nxt -= 3;
            LOADKV(nxt, kt + 2);
        }
        const uint32_t kb = sb + AT_STG + (uint32_t)cur * KVSTG;

        float s[8][4];
        #pragma unroll
        for (int j = 0; j < 8; j++)
            #pragma unroll
            for (int e = 0; e < 4; e++) s[j][e] = 0.f;

        #pragma unroll
        for (int ks = 0; ks < 4; ks++) {
            uint32_t ah[4];
            uint32_t aaddr = sb + AT_Q + (uint32_t)rA * 128
                           + (uint32_t)(((ks * 2 + (lane >> 4)) ^ (rA & 7)) << 4);
            LDSM4(ah, aaddr);
            #pragma unroll
            for (int np = 0; np < 4; np++) {
                int rB = np * 16 + rBb;
                uint32_t baddr = kb + (uint32_t)rB * 128
                               + (uint32_t)(((ks * 2 + ((lane >> 3) & 1)) ^ (rB & 7)) << 4);
                uint32_t bhF[4];
                LDSM4(bhF, baddr);
                #pragma unroll
                for (int hf = 0; hf < 2; hf++) {
                    int nt = np * 2 + hf, rb = hf * 2;
                    MMA16816(s[nt], ah, bhF[rb], bhF[rb + 1]);
                }
            }
        }

        float mx0 = -INFINITY, mx1 = -INFINITY;
        #pragma unroll
        for (int j = 0; j < 8; j++) {
            float2 mk = *(float2*)(smraw + AT_MASK + (size_t)(kt * 64 + j * 8 + c2) * 4);
            s[j][0] = s[j][0] * 0.125f + mk.x;
            s[j][1] = s[j][1] * 0.125f + mk.y;
            s[j][2] = s[j][2] * 0.125f + mk.x;
            s[j][3] = s[j][3] * 0.125f + mk.y;
            mx0 = fmaxf(mx0, fmaxf(s[j][0], s[j][1]));
            mx1 = fmaxf(mx1, fmaxf(s[j][2], s[j][3]));
        }
        #pragma unroll
        for (int off = 1; off < 4; off <<= 1) {
            mx0 = fmaxf(mx0, __shfl_xor_sync(0xffffffffu, mx0, off));
            mx1 = fmaxf(mx1, __shfl_xor_sync(0xffffffffu, mx1, off));
        }
        float mn0 = fmaxf(m0, mx0), mn1 = fmaxf(m1, mx1);
        float corr0 = __expf(m0 - mn0), corr1 = __expf(m1 - mn1);
        m0 = mn0; m1 = mn1;
        float sum0 = 0.f, sum1 = 0.f;
        #pragma unroll
        for (int j = 0; j < 8; j++) {
            s[j][0] = __expf(s[j][0] - m0);
            s[j][1] = __expf(s[j][1] - m0);
            s[j][2] = __expf(s[j][2] - m1);
            s[j][3] = __expf(s[j][3] - m1);
            sum0 += s[j][0] + s[j][1];
            sum1 += s[j][2] + s[j][3];
        }
        #pragma unroll
        for (int off = 1; off < 4; off <<= 1) {
            sum0 += __shfl_xor_sync(0xffffffffu, sum0, off);
            sum1 += __shfl_xor_sync(0xffffffffu, sum1, off);
        }
        l0 = l0 * corr0 + sum0;
        l1 = l1 * corr1 + sum1;
        #pragma unroll
        for (int j = 0; j < 8; j++) {
            o[j][0] *= corr0; o[j][1] *= corr0;
            o[j][2] *= corr1; o[j][3] *= corr1;
        }

        #pragma unroll
        for (int kg = 0; kg < 4; kg++) {
            uint32_t ph[4];
            ph[0] = pack2h(s[2*kg][0],   s[2*kg][1]);
            ph[1] = pack2h(s[2*kg][2],   s[2*kg][3]);
            ph[2] = pack2h(s[2*kg+1][0], s[2*kg+1][1]);
            ph[3] = pack2h(s[2*kg+1][2], s[2*kg+1][3]);
            int rV = kg * 16 + (lane & 15);
            #pragma unroll
            for (int np = 0; np < 4; np++) {
                uint32_t vaddr = kb + 8192 + (uint32_t)rV * 128
                               + (uint32_t)(((np * 2 + (lane >> 4)) ^ (rV & 7)) << 4);
                uint32_t vhF[4];
                LDSM4T(vhF, vaddr);
                #pragma unroll
                for (int hf = 0; hf < 2; hf++) {
                    int nt = np * 2 + hf, rb = hf * 2;
                    MMA16816(o[nt], ph, vhF[rb], vhF[rb + 1]);
                }
            }
        }

        cur++;
        if (cur == 3) cur = 0;
    }

    float i0 = 1.0f / l0, i1 = 1.0f / l1;
    size_t row0 = (size_t)b * 1024 + qt * 128 + w * 16 + (lane >> 2);
    #pragma unroll
    for (int j = 0; j < 8; j++) {
        int col = h * 64 + j * 8 + c2;
        *(uint32_t*)(chi + row0 * D_ + col)       = pack2h(o[j][0] * i0, o[j][1] * i0);
        *(uint32_t*)(chi + (row0 + 8) * D_ + col) = pack2h(o[j][2] * i1, o[j][3] * i1);
    }
    #undef LOADKV
}

// ---------------------------------------------------------------------------
// LayerNorm over last dim (1024).
// ---------------------------------------------------------------------------
__global__ __launch_bounds__(256) void lnorm(
    const float* __restrict__ X, const float* __restrict__ hsc,
    const float* __restrict__ hbi, float* __restrict__ out)
{
    int row = blockIdx.x;
    int c4 = threadIdx.x * 4;
    const float* x = X + (size_t)row * D_;
    float4 v = *(const float4*)(x + c4);
    float sum = v.x + v.y + v.z + v.w;
    float sq  = v.x*v.x + v.y*v.y + v.z*v.z + v.w*v.w;
    #pragma unroll
    for (int off = 16; off > 0; off >>= 1) {
        sum += __shfl_xor_sync(0xffffffffu, sum, off);
        sq  += __shfl_xor_sync(0xffffffffu, sq,  off);
    }
    __shared__ float rs[8], rq[8];
    int warp = threadIdx.x >> 5;
    if ((threadIdx.x & 31) == 0) { rs[warp] = sum; rq[warp] = sq; }
    __syncthreads();
    float tot = 0.f, totq = 0.f;
    #pragma unroll
    for (int wv = 0; wv < 8; wv++) { tot += rs[wv]; totq += rq[wv]; }
    float mu  = tot  * (1.0f / 1024.0f);
    float var = totq * (1.0f / 1024.0f) - mu * mu;
    float inv = rsqrtf(var + 1e-12f);
    float4 sc = *(const float4*)(hsc + c4);
    float4 bi = *(const float4*)(hbi + c4);
    float4 oo;
    oo.x = (v.x - mu) * inv * sc.x + bi.x;
    oo.y = (v.y - mu) * inv * sc.y + bi.y;
    oo.z = (v.z - mu) * inv * sc.z + bi.z;
    oo.w = (v.w - mu) * inv * sc.w + bi.w;
    *(float4*)&out[(size_t)row * D_ + c4] = oo;
}

// ---------------------------------------------------------------------------
extern "C" void kernel_launch(void* const* d_in, const int* in_sizes, int n_in,
                              void* d_out, int out_size)
{
    const float* hidden = (const float*)d_in[0];
    const float* mask   = (const float*)d_in[1];
    const float* phi    = (const float*)d_in[2];
    const float* mag    = (const float*)d_in[3];
    const float* Wq     = (const float*)d_in[4];
    const float* bq     = (const float*)d_in[5];
    const float* Wk     = (const float*)d_in[6];
    const float* bk     = (const float*)d_in[7];
    const float* Wv     = (const float*)d_in[8];
    const float* bv     = (const float*)d_in[9];
    const float* gamma  = (const float*)d_in[10];
    const float* Wo     = (const float*)d_in[11];
    const float* bo     = (const float*)d_in[12];
    const float* lns    = (const float*)d_in[13];
    const float* lnb    = (const float*)d_in[14];
    float* out = (float*)d_out;

    float *x;
    float4* prp;
    __half *ahi, *w16, *qhi, *khi, *vhi;
    cudaGetSymbolAddress((void**)&x,   g_x);
    cudaGetSymbolAddress((void**)&prp, g_prep);
    cudaGetSymbolAddress((void**)&ahi, g_ahi);
    cudaGetSymbolAddress((void**)&w16, g_w16);
    cudaGetSymbolAddress((void**)&qhi, g_qhi);
    cudaGetSymbolAddress((void**)&khi, g_khi);
    cudaGetSymbolAddress((void**)&vhi, g_vhi);

    cudaFuncSetAttribute(gemm_hmma, cudaFuncAttributeMaxDynamicSharedMemorySize, GEMM_DYN);
    cudaFuncSetAttribute(attn_hmma, cudaFuncAttributeMaxDynamicSharedMemorySize, ATTN_DYN);

    const int DD = D_ * D_;

    // fused prelude: z=0 convA, z=1 convW (streaming), z=2 prep
    prelude<<<dim3(4096, 1, 3), 256>>>(
        (const float4*)hidden,
        (const float4*)Wq, (const float4*)Wk, (const float4*)Wv, (const float4*)Wo,
        phi, mag, gamma,
        (uint2*)ahi, (uint2*)w16, prp);

    // QKV fused (z: 0=Q rot, 1=K rot, 2=V), fp16 head-major outputs
    gemm_hmma<<<dim3(D_ / GN, M_TOT / GM, 3), 256, GEMM_DYN>>>(
        ahi, w16, bq, bk, bv, prp, qhi, khi, vhi, nullptr, nullptr);

    attn_hmma<<<dim3(L_ / 128, B_ * H_), 256, ATTN_DYN>>>(
        qhi, khi, vhi, mask, ahi);

    // Wo projection + residual
    gemm_hmma<<<dim3(D_ / GN, M_TOT / GM, 1), 256, GEMM_DYN>>>(
        ahi, w16 + 3*DD, bo, bo, bo, prp,
        nullptr, nullptr, nullptr, hidden, x);

    lnorm<<<M_TOT, 256>>>(x, lns, lnb, out);
}

// round 14
// speedup vs baseline: 1.4847x; 1.4847x over previous
#include <cuda_runtime.h>
#include <cuda_fp16.h>
#include <math.h>
#include <stdint.h>

#define B_  4
#define L_  1024
#define D_  1024
#define H_  16
#define HD_ 64
#define M_TOT (B_*L_)   // 4096

// ---------------------------------------------------------------------------
// Scratch
// ---------------------------------------------------------------------------
__device__ float g_x[M_TOT * D_];
__device__ float4 g_prep[B_ * H_ * L_];     // (sc, sin, cos, 0) per (bh,l)
__device__ __half g_ahi[M_TOT * D_];        // activations / ctx fp16
__device__ __half g_wthi[4 * D_ * D_];      // W^T [N][K] fp16 (q,k,v,o)
__device__ __half g_qhi[M_TOT * D_];        // rotated Q fp16, head-major
__device__ __half g_khi[M_TOT * D_];        // rotated K fp16, head-major
__device__ __half g_vhi[M_TOT * D_];        // V fp16, head-major

// ---------------------------------------------------------------------------
// Helpers
// ---------------------------------------------------------------------------
__device__ __forceinline__ uint32_t smem_to_u32(const void* p) {
    uint32_t a;
    asm("{ .reg .u64 t; cvta.to.shared.u64 t, %1; cvt.u32.u64 %0, t; }"
        : "=r"(a) : "l"(p));
    return a;
}

#define CP16(dst, src) \
    asm volatile("cp.async.cg.shared.global [%0], [%1], 16;" \
                 :: "r"(dst), "l"(src) : "memory")
#define CP_COMMIT() asm volatile("cp.async.commit_group;" ::: "memory")
#define CP_WAIT(n)  asm volatile("cp.async.wait_group %0;" :: "n"(n) : "memory")

#define LDSM4(r, addr) \
    asm volatile("ldmatrix.sync.aligned.m8n8.x4.shared.b16 {%0,%1,%2,%3}, [%4];" \
                 : "=r"((r)[0]), "=r"((r)[1]), "=r"((r)[2]), "=r"((r)[3]) : "r"(addr))
#define LDSM4T(r, addr) \
    asm volatile("ldmatrix.sync.aligned.m8n8.x4.trans.shared.b16 {%0,%1,%2,%3}, [%4];" \
                 : "=r"((r)[0]), "=r"((r)[1]), "=r"((r)[2]), "=r"((r)[3]) : "r"(addr))

#define MMA16816(c, a, b0, b1) \
    asm volatile("mma.sync.aligned.m16n8k16.row.col.f32.f16.f16.f32 " \
                 "{%0,%1,%2,%3}, {%4,%5,%6,%7}, {%8,%9}, {%0,%1,%2,%3};" \
                 : "+f"((c)[0]), "+f"((c)[1]), "+f"((c)[2]), "+f"((c)[3]) \
                 : "r"((a)[0]), "r"((a)[1]), "r"((a)[2]), "r"((a)[3]), \
                   "r"(b0), "r"(b1))

// pack two floats -> fp16x2 (x in low half)
__device__ __forceinline__ uint32_t pack2h(float x, float y) {
    uint32_t d;
    asm("cvt.rn.f16x2.f32 %0, %1, %2;" : "=r"(d) : "f"(y), "f"(x));
    return d;
}

// ---------------------------------------------------------------------------
// prelude (fused, grid 32x32x6):
//  z=0..3: W[K,N] fp32 -> WT[N,K] fp16 (tiled transpose, half2 stores)
//  z=4:    convA (hidden fp32 -> fp16) -- 4 float4 per thread (full coverage)
//  z=5:    prep (scale/sin/cos), first 256 blocks only
// ---------------------------------------------------------------------------
__global__ __launch_bounds__(256) void prelude(
    const float* __restrict__ Wq, const float* __restrict__ Wk,
    const float* __restrict__ Wv, const float* __restrict__ Wo,
    const float4* __restrict__ hidden,
    const float* __restrict__ phi, const float* __restrict__ mag,
    const float* __restrict__ gamma,
    __half* __restrict__ wt, uint2* __restrict__ ahi,
    float4* __restrict__ prp)
{
    const int z = blockIdx.z;
    if (z < 4) {
        __shared__ float t[32][33];
        const float* W = (z == 0) ? Wq : (z == 1) ? Wk : (z == 2) ? Wv : Wo;
        __half* hz = wt + (size_t)z * D_ * D_;
        int n0 = blockIdx.x * 32, k0 = blockIdx.y * 32;
        int tx = threadIdx.x & 31, ty = threadIdx.x >> 5;
        #pragma unroll
        for (int j = 0; j < 4; j++)
            t[ty + j*8][tx] = W[(size_t)(k0 + ty + j*8) * D_ + n0 + tx];
        __syncthreads();
        // half2 stores along K: thread (tn, tk) writes n = n0+tn(+16), k = k0+2tk..+1
        int tk = threadIdx.x & 15, tn = threadIdx.x >> 4;
        #pragma unroll
        for (int half_ = 0; half_ < 2; half_++) {
            int n = tn + half_ * 16;
            uint32_t pk = pack2h(t[2*tk][n], t[2*tk+1][n]);
            *(uint32_t*)(hz + (size_t)(n0 + n) * D_ + k0 + 2*tk) = pk;
        }
    } else if (z == 4) {
        // convA: 1048576 float4 total; 262144 threads -> 4 each
        int base = (blockIdx.y * 32 + blockIdx.x) * 256 + threadIdx.x;
        #pragma unroll
        for (int it = 0; it < 4; it++) {
            int i = base + it * 262144;
            float4 v = hidden[i];
            uint2 ho;
            ho.x = pack2h(v.x, v.y);
            ho.y = pack2h(v.z, v.w);
            ahi[i] = ho;
        }
    } else {
        int blk = blockIdx.y * 32 + blockIdx.x;
        if (blk >= 256) return;
        int i = blk * 256 + threadIdx.x;          // < 65536
        int h = (i >> 10) & 15;
        float sc = 1.0f + gamma[h] * tanhf(mag[i]);
        float s, c;
        sincosf(phi[i], &s, &c);
        prp[i] = make_float4(sc, s, c, 0.f);
    }
}

// ---------------------------------------------------------------------------
// HMMA fp16 GEMM (R11 config): 128x128 CTA tile, 256 threads = 8 warps
// (32x64 tiles), 3-stage cp.async pipeline, 2 CTAs/SM, B in [N][K] layout.
// Modes:
//  res == nullptr, z=0/1: Q/K -> bias+scale+rotate -> fp16 head-major
//  res == nullptr, z=2:   V  -> bias -> fp16 head-major
//  res != nullptr:        Wo -> bias + residual -> fp32 row-major
// ---------------------------------------------------------------------------
#define GM 128
#define GN 128
#define KC 64
#define OFF_BHI  16384
#define STAGE    32768
#define NSTG     3
#define GEMM_DYN (NSTG*STAGE)   // 98304

__global__ __launch_bounds__(256, 2) void gemm_hmma(
    const __half* __restrict__ Ahi,
    const __half* __restrict__ WThi,
    const float* __restrict__ bias0, const float* __restrict__ bias1,
    const float* __restrict__ bias2,
    const float4* __restrict__ prp,
    __half* __restrict__ qh, __half* __restrict__ kh,
    __half* __restrict__ vh,
    const float* __restrict__ res, float* __restrict__ xout)
{
    extern __shared__ char smraw[];
    const uint32_t sbase = smem_to_u32(smraw);
    const int tid  = threadIdx.x;
    const int lane = tid & 31, wid = tid >> 5;
    const int wm = wid >> 1, wn = wid & 1;    // 4 x 2 warps of 32x64
    const int bm = blockIdx.y * GM, bn = blockIdx.x * GN;
    const int z  = blockIdx.z;

    const __half* Bh = WThi + (size_t)z * D_ * D_;
    const float* bias = (z == 0) ? bias0 : (z == 1) ? bias1 : bias2;

    const int rr  = tid >> 3;     // 0..31
    const int seg = tid & 7;

    #define LOAD_STAGE(s, kc) do { \
        uint32_t sb_ = sbase + (uint32_t)(s) * STAGE; \
        _Pragma("unroll") \
        for (int h4 = 0; h4 < 4; h4++) { \
            int r_ = rr + h4 * 32; \
            uint32_t sw_ = (uint32_t)r_ * 128 + (uint32_t)((seg ^ (r_ & 7)) << 4); \
            size_t ga_ = (size_t)(bm + r_) * D_ + (kc) + seg * 8; \
            size_t gb_ = (size_t)(bn + r_) * D_ + (kc) + seg * 8; \
            CP16(sb_ + sw_,           Ahi + ga_); \
            CP16(sb_ + OFF_BHI + sw_, Bh + gb_); \
        } \
        CP_COMMIT(); \
    } while (0)

    float c[2][8][4];
    #pragma unroll
    for (int mi = 0; mi < 2; mi++)
        #pragma unroll
        for (int ni = 0; ni < 8; ni++)
            #pragma unroll
            for (int e = 0; e < 4; e++) c[mi][ni][e] = 0.f;

    LOAD_STAGE(0, 0);
    LOAD_STAGE(1, KC);

    const int rAb = wm * 32 + (lane & 15);
    const int rBb = wn * 64 + ((lane >> 4) << 3) + (lane & 7);
    const int sgA = lane >> 4;
    const int sgB = (lane >> 3) & 1;

    int cur = 0;
    for (int ch = 0; ch < 16; ch++) {
        if (ch < 15) CP_WAIT(1);
        else         CP_WAIT(0);
        __syncthreads();
        if (ch < 14) {
            int nxt = cur + 2;
            if (nxt >= 3) nxt -= 3;
            LOAD_STAGE(nxt, (ch + 2) * KC);
        }

        const uint32_t sb = sbase + (uint32_t)cur * STAGE;
        #pragma unroll
        for (int ks = 0; ks < 4; ks++) {
            uint32_t ah[2][4];
            #pragma unroll
            for (int mi = 0; mi < 2; mi++) {
                int rA = rAb + mi * 16;
                uint32_t addr = sb + (uint32_t)rA * 128
                              + (uint32_t)(((ks * 2 + sgA) ^ (rA & 7)) << 4);
                LDSM4(ah[mi], addr);
            }
            #pragma unroll
            for (int np = 0; np < 4; np++) {
                int rB = rBb + np * 16;
                uint32_t addr = sb + OFF_BHI + (uint32_t)rB * 128
                              + (uint32_t)(((ks * 2 + sgB) ^ (rB & 7)) << 4);
                uint32_t bh[4];
                LDSM4(bh, addr);
                #pragma unroll
                for (int hf = 0; hf < 2; hf++) {
                    int ni = np * 2 + hf, rb = hf * 2;
                    #pragma unroll
                    for (int mi = 0; mi < 2; mi++)
                        MMA16816(c[mi][ni], ah[mi], bh[rb], bh[rb + 1]);
                }
            }
        }
        cur++;
        if (cur == 3) cur = 0;
    }

    // ---- epilogue ----
    const int g = lane >> 2, tig = lane & 3;
    if (res) {
        // Wo projection + bias + residual -> fp32 row-major
        #pragma unroll
        for (int mi = 0; mi < 2; mi++) {
            int row0 = bm + wm * 32 + mi * 16 + g;
            #pragma unroll
            for (int ni = 0; ni < 8; ni++) {
                int col = bn + wn * 64 + ni * 8 + tig * 2;
                float2 bv = *(const float2*)(bias + col);
                float2 r0 = *(const float2*)(res + (size_t)row0 * D_ + col);
                float2 r1 = *(const float2*)(res + (size_t)(row0 + 8) * D_ + col);
                *(float2*)(xout + (size_t)row0 * D_ + col) =
                    make_float2(c[mi][ni][0] + bv.x + r0.x, c[mi][ni][1] + bv.y + r0.y);
                *(float2*)(xout + (size_t)(row0 + 8) * D_ + col) =
                    make_float2(c[mi][ni][2] + bv.x + r1.x, c[mi][ni][3] + bv.y + r1.y);
            }
        }
    } else if (z == 2) {
        // V: bias -> fp16 head-major
        #pragma unroll
        for (int mi = 0; mi < 2; mi++) {
            int row0 = bm + wm * 32 + mi * 16 + g;
            int bidx = row0 >> 10, l0 = row0 & 1023;
            #pragma unroll
            for (int ni = 0; ni < 8; ni++) {
                int col = bn + wn * 64 + ni * 8 + tig * 2;
                float2 bv = *(const float2*)(bias + col);
                size_t o0 = (((size_t)bidx * 16 + (col >> 6)) * 1024 + l0) * 64 + (col & 63);
                size_t o1 = o0 + 8 * 64;
                *(uint32_t*)(vh + o0) = pack2h(c[mi][ni][0] + bv.x, c[mi][ni][1] + bv.y);
                *(uint32_t*)(vh + o1) = pack2h(c[mi][ni][2] + bv.x, c[mi][ni][3] + bv.y);
            }
        }
    } else {
        // Q/K: bias + scale + rotate -> fp16 head-major
        __half* oh = (z == 0) ? qh : kh;
        const int hh = (bn + wn * 64) >> 6;
        #pragma unroll
        for (int mi = 0; mi < 2; mi++) {
            int row0 = bm + wm * 32 + mi * 16 + g;
            int bidx = row0 >> 10, l0 = row0 & 1023;
            int pidx = (bidx * 16 + hh) * 1024 + l0;
            float4 p0 = prp[pidx];
            float4 p1 = prp[pidx + 8];
            size_t ob = ((size_t)(bidx * 16 + hh) * 1024 + l0) * 64;
            #pragma unroll
            for (int ni = 0; ni < 4; ni++) {
                int d = ni * 8 + tig * 2;
                float2 b1 = *(const float2*)(bias + bn + wn * 64 + d);
                float2 b2 = *(const float2*)(bias + bn + wn * 64 + d + 32);
                // row0
                {
                    float x0 = (c[mi][ni][0]   + b1.x) * p0.x;
                    float x1 = (c[mi][ni][1]   + b1.y) * p0.x;
                    float y0 = (c[mi][ni+4][0] + b2.x) * p0.x;
                    float y1 = (c[mi][ni+4][1] + b2.y) * p0.x;
                    *(uint32_t*)(oh + ob + d) =
                        pack2h(x0 * p0.z - y0 * p0.y, x1 * p0.z - y1 * p0.y);
                    *(uint32_t*)(oh + ob + d + 32) =
                        pack2h(y0 * p0.z + x0 * p0.y, y1 * p0.z + x1 * p0.y);
                }
                // row0 + 8
                {
                    float x0 = (c[mi][ni][2]   + b1.x) * p1.x;
                    float x1 = (c[mi][ni][3]   + b1.y) * p1.x;
                    float y0 = (c[mi][ni+4][2] + b2.x) * p1.x;
                    float y1 = (c[mi][ni+4][3] + b2.y) * p1.x;
                    *(uint32_t*)(oh + ob + 512 + d) =
                        pack2h(x0 * p1.z - y0 * p1.y, x1 * p1.z - y1 * p1.y);
                    *(uint32_t*)(oh + ob + 512 + d + 32) =
                        pack2h(y0 * p1.z + x0 * p1.y, y1 * p1.z + x1 * p1.y);
                }
            }
        }
    }
    #undef LOAD_STAGE
}

// ---------------------------------------------------------------------------
// HMMA fp16 flash attention, 1-term, 3-stage KV pipeline (R11, unchanged).
// ---------------------------------------------------------------------------
#define AT_Q   0
#define AT_STG 16384
#define KVSTG  16384                  // K @0, V @8192
#define AT_MASK (AT_STG + 3*KVSTG)    // 65536
#define ATTN_DYN (AT_MASK + 4096)     // 69632

__global__ __launch_bounds__(256, 2) void attn_hmma(
    const __half* __restrict__ qhi,
    const __half* __restrict__ khi,
    const __half* __restrict__ vhi,
    const float* __restrict__ mask,
    __half* __restrict__ chi)
{
    extern __shared__ char smraw[];
    const uint32_t sb = smem_to_u32(smraw);
    const int tid = threadIdx.x, lane = tid & 31, w = tid >> 5;
    const int qt = blockIdx.x, bh = blockIdx.y;
    const int b = bh >> 4, h = bh & 15;

    CP16(sb + AT_MASK + tid * 16, mask + b * 1024 + tid * 4);
    #pragma unroll
    for (int it = 0; it < 4; it++) {
        int idx = tid + it * 256, r = idx >> 3, seg = idx & 7;
        size_t g = ((size_t)bh * 1024 + qt * 128 + r) * 64 + seg * 8;
        uint32_t d = sb + (uint32_t)r * 128 + (uint32_t)((seg ^ (r & 7)) << 4);
        CP16(d + AT_Q, qhi + g);
    }
    CP_COMMIT();

    #define LOADKV(s, kt_) do { \
        _Pragma("unroll") \
        for (int it = 0; it < 2; it++) { \
            int idx = tid + it * 256, r = idx >> 3, sg = idx & 7; \
            size_t g = ((size_t)bh * 1024 + (kt_) * 64 + r) * 64 + sg * 8; \
            uint32_t d = sb + AT_STG + (uint32_t)(s) * KVSTG \
                       + (uint32_t)r * 128 + (uint32_t)((sg ^ (r & 7)) << 4); \
            CP16(d,        khi + g); \
            CP16(d + 8192, vhi + g); \
        } \
        CP_COMMIT(); \
    } while (0)

    LOADKV(0, 0);
    LOADKV(1, 1);

    float o[8][4];
    #pragma unroll
    for (int j = 0; j < 8; j++)
        #pragma unroll
        for (int e = 0; e < 4; e++) o[j][e] = 0.f;
    float m0 = -INFINITY, m1 = -INFINITY, l0 = 0.f, l1 = 0.f;

    const int rA = w * 16 + (lane & 15);
    const int rBb = ((lane >> 4) << 3) + (lane & 7);
    const int c2 = (lane & 3) * 2;

    int cur = 0;
    for (int kt = 0; kt < 16; kt++) {
        if (kt < 15) CP_WAIT(1);
        else         CP_WAIT(0);
        __syncthreads();
        if (kt < 14) {
            int nxt = cur + 2;
            if (nxt >= 3) nxt -= 3;
            LOADKV(nxt, kt + 2);
        }
        const uint32_t kb = sb + AT_STG + (uint32_t)cur * KVSTG;

        float s[8][4];
        #pragma unroll
        for (int j = 0; j < 8; j++)
            #pragma unroll
            for (int e = 0; e < 4; e++) s[j][e] = 0.f;

        #pragma unroll
        for (int ks = 0; ks < 4; ks++) {
            uint32_t ah[4];
            uint32_t aaddr = sb + AT_Q + (uint32_t)rA * 128
                           + (uint32_t)(((ks * 2 + (lane >> 4)) ^ (rA & 7)) << 4);
            LDSM4(ah, aaddr);
            #pragma unroll
            for (int np = 0; np < 4; np++) {
                int rB = np * 16 + rBb;
                uint32_t baddr = kb + (uint32_t)rB * 128
                               + (uint32_t)(((ks * 2 + ((lane >> 3) & 1)) ^ (rB & 7)) << 4);
                uint32_t bhF[4];
                LDSM4(bhF, baddr);
                #pragma unroll
                for (int hf = 0; hf < 2; hf++) {
                    int nt = np * 2 + hf, rb = hf * 2;
                    MMA16816(s[nt], ah, bhF[rb], bhF[rb + 1]);
                }
            }
        }

        float mx0 = -INFINITY, mx1 = -INFINITY;
        #pragma unroll
        for (int j = 0; j < 8; j++) {
            float2 mk = *(float2*)(smraw + AT_MASK + (size_t)(kt * 64 + j * 8 + c2) * 4);
            s[j][0] = s[j][0] * 0.125f + mk.x;
            s[j][1] = s[j][1] * 0.125f + mk.y;
            s[j][2] = s[j][2] * 0.125f + mk.x;
            s[j][3] = s[j][3] * 0.125f + mk.y;
            mx0 = fmaxf(mx0, fmaxf(s[j][0], s[j][1]));
            mx1 = fmaxf(mx1, fmaxf(s[j][2], s[j][3]));
        }
        #pragma unroll
        for (int off = 1; off < 4; off <<= 1) {
            mx0 = fmaxf(mx0, __shfl_xor_sync(0xffffffffu, mx0, off));
            mx1 = fmaxf(mx1, __shfl_xor_sync(0xffffffffu, mx1, off));
        }
        float mn0 = fmaxf(m0, mx0), mn1 = fmaxf(m1, mx1);
        float corr0 = __expf(m0 - mn0), corr1 = __expf(m1 - mn1);
        m0 = mn0; m1 = mn1;
        float sum0 = 0.f, sum1 = 0.f;
        #pragma unroll
        for (int j = 0; j < 8; j++) {
            s[j][0] = __expf(s[j][0] - m0);
            s[j][1] = __expf(s[j][1] - m0);
            s[j][2] = __expf(s[j][2] - m1);
            s[j][3] = __expf(s[j][3] - m1);
            sum0 += s[j][0] + s[j][1];
            sum1 += s[j][2] + s[j][3];
        }
        #pragma unroll
        for (int off = 1; off < 4; off <<= 1) {
            sum0 += __shfl_xor_sync(0xffffffffu, sum0, off);
            sum1 += __shfl_xor_sync(0xffffffffu, sum1, off);
        }
        l0 = l0 * corr0 + sum0;
        l1 = l1 * corr1 + sum1;
        #pragma unroll
        for (int j = 0; j < 8; j++) {
            o[j][0] *= corr0; o[j][1] *= corr0;
            o[j][2] *= corr1; o[j][3] *= corr1;
        }

        #pragma unroll
        for (int kg = 0; kg < 4; kg++) {
            uint32_t ph[4];
            ph[0] = pack2h(s[2*kg][0],   s[2*kg][1]);
            ph[1] = pack2h(s[2*kg][2],   s[2*kg][3]);
            ph[2] = pack2h(s[2*kg+1][0], s[2*kg+1][1]);
            ph[3] = pack2h(s[2*kg+1][2], s[2*kg+1][3]);
            int rV = kg * 16 + (lane & 15);
            #pragma unroll
            for (int np = 0; np < 4; np++) {
                uint32_t vaddr = kb + 8192 + (uint32_t)rV * 128
                               + (uint32_t)(((np * 2 + (lane >> 4)) ^ (rV & 7)) << 4);
                uint32_t vhF[4];
                LDSM4T(vhF, vaddr);
                #pragma unroll
                for (int hf = 0; hf < 2; hf++) {
                    int nt = np * 2 + hf, rb = hf * 2;
                    MMA16816(o[nt], ph, vhF[rb], vhF[rb + 1]);
                }
            }
        }

        cur++;
        if (cur == 3) cur = 0;
    }

    float i0 = 1.0f / l0, i1 = 1.0f / l1;
    size_t row0 = (size_t)b * 1024 + qt * 128 + w * 16 + (lane >> 2);
    #pragma unroll
    for (int j = 0; j < 8; j++) {
        int col = h * 64 + j * 8 + c2;
        *(uint32_t*)(chi + row0 * D_ + col)       = pack2h(o[j][0] * i0, o[j][1] * i0);
        *(uint32_t*)(chi + (row0 + 8) * D_ + col) = pack2h(o[j][2] * i1, o[j][3] * i1);
    }
    #undef LOADKV
}

// ---------------------------------------------------------------------------
// LayerNorm over last dim (1024).
// ---------------------------------------------------------------------------
__global__ __launch_bounds__(256) void lnorm(
    const float* __restrict__ X, const float* __restrict__ hsc,
    const float* __restrict__ hbi, float* __restrict__ out)
{
    int row = blockIdx.x;
    int c4 = threadIdx.x * 4;
    const float* x = X + (size_t)row * D_;
    float4 v = *(const float4*)(x + c4);
    float sum = v.x + v.y + v.z + v.w;
    float sq  = v.x*v.x + v.y*v.y + v.z*v.z + v.w*v.w;
    #pragma unroll
    for (int off = 16; off > 0; off >>= 1) {
        sum += __shfl_xor_sync(0xffffffffu, sum, off);
        sq  += __shfl_xor_sync(0xffffffffu, sq,  off);
    }
    __shared__ float rs[8], rq[8];
    int warp = threadIdx.x >> 5;
    if ((threadIdx.x & 31) == 0) { rs[warp] = sum; rq[warp] = sq; }
    __syncthreads();
    float tot = 0.f, totq = 0.f;
    #pragma unroll
    for (int wv = 0; wv < 8; wv++) { tot += rs[wv]; totq += rq[wv]; }
    float mu  = tot  * (1.0f / 1024.0f);
    float var = totq * (1.0f / 1024.0f) - mu * mu;
    float inv = rsqrtf(var + 1e-12f);
    float4 sc = *(const float4*)(hsc + c4);
    float4 bi = *(const float4*)(hbi + c4);
    float4 oo;
    oo.x = (v.x - mu) * inv * sc.x + bi.x;
    oo.y = (v.y - mu) * inv * sc.y + bi.y;
    oo.z = (v.z - mu) * inv * sc.z + bi.z;
    oo.w = (v.w - mu) * inv * sc.w + bi.w;
    *(float4*)&out[(size_t)row * D_ + c4] = oo;
}

// ---------------------------------------------------------------------------
extern "C" void kernel_launch(void* const* d_in, const int* in_sizes, int n_in,
                              void* d_out, int out_size)
{
    const float* hidden = (const float*)d_in[0];
    const float* mask   = (const float*)d_in[1];
    const float* phi    = (const float*)d_in[2];
    const float* mag    = (const float*)d_in[3];
    const float* Wq     = (const float*)d_in[4];
    const float* bq     = (const float*)d_in[5];
    const float* Wk     = (const float*)d_in[6];
    const float* bk     = (const float*)d_in[7];
    const float* Wv     = (const float*)d_in[8];
    const float* bv     = (const float*)d_in[9];
    const float* gamma  = (const float*)d_in[10];
    const float* Wo     = (const float*)d_in[11];
    const float* bo     = (const float*)d_in[12];
    const float* lns    = (const float*)d_in[13];
    const float* lnb    = (const float*)d_in[14];
    float* out = (float*)d_out;

    float *x;
    float4* prp;
    __half *ahi, *wthi, *qhi, *khi, *vhi;
    cudaGetSymbolAddress((void**)&x,    g_x);
    cudaGetSymbolAddress((void**)&prp,  g_prep);
    cudaGetSymbolAddress((void**)&ahi,  g_ahi);
    cudaGetSymbolAddress((void**)&wthi, g_wthi);
    cudaGetSymbolAddress((void**)&qhi,  g_qhi);
    cudaGetSymbolAddress((void**)&khi,  g_khi);
    cudaGetSymbolAddress((void**)&vhi,  g_vhi);

    cudaFuncSetAttribute(gemm_hmma, cudaFuncAttributeMaxDynamicSharedMemorySize, GEMM_DYN);
    cudaFuncSetAttribute(attn_hmma, cudaFuncAttributeMaxDynamicSharedMemorySize, ATTN_DYN);

    const int DD = D_ * D_;

    // fused prelude: z=0..3 convW transpose, z=4 convA, z=5 prep
    prelude<<<dim3(32, 32, 6), 256>>>(
        Wq, Wk, Wv, Wo, (const float4*)hidden, phi, mag, gamma,
        wthi, (uint2*)ahi, prp);

    // QKV fused (z: 0=Q rot, 1=K rot, 2=V), fp16 head-major outputs
    gemm_hmma<<<dim3(D_ / GN, M_TOT / GM, 3), 256, GEMM_DYN>>>(
        ahi, wthi, bq, bk, bv, prp, qhi, khi, vhi, nullptr, nullptr);

    attn_hmma<<<dim3(L_ / 128, B_ * H_), 256, ATTN_DYN>>>(
        qhi, khi, vhi, mask, ahi);

    // Wo projection + residual
    gemm_hmma<<<dim3(D_ / GN, M_TOT / GM, 1), 256, GEMM_DYN>>>(
        ahi, wthi + 3*DD, bo, bo, bo, prp,
        nullptr, nullptr, nullptr, hidden, x);

    lnorm<<<M_TOT, 256>>>(x, lns, lnb, out);
}

// round 15
// speedup vs baseline: 1.4935x; 1.0059x over previous
#include <cuda_runtime.h>
#include <cuda_fp16.h>
#include <math.h>
#include <stdint.h>

#define B_  4
#define L_  1024
#define D_  1024
#define H_  16
#define HD_ 64
#define M_TOT (B_*L_)   // 4096

// ---------------------------------------------------------------------------
// Scratch
// ---------------------------------------------------------------------------
__device__ float g_x[M_TOT * D_];
__device__ float4 g_prep[B_ * H_ * L_];     // (sc, sin, cos, 0) per (bh,l)
__device__ __half g_ahi[M_TOT * D_];        // activations / ctx fp16
__device__ __half g_wthi[4 * D_ * D_];      // W^T [N][K] fp16 (q,k,v,o)
__device__ __half g_qhi[M_TOT * D_];        // rotated Q fp16 (pre-scaled), head-major
__device__ __half g_khi[M_TOT * D_];        // rotated K fp16, head-major
__device__ __half g_vhi[M_TOT * D_];        // V fp16, head-major

// ---------------------------------------------------------------------------
// Helpers
// ---------------------------------------------------------------------------
__device__ __forceinline__ uint32_t smem_to_u32(const void* p) {
    uint32_t a;
    asm("{ .reg .u64 t; cvta.to.shared.u64 t, %1; cvt.u32.u64 %0, t; }"
        : "=r"(a) : "l"(p));
    return a;
}

#define CP16(dst, src) \
    asm volatile("cp.async.cg.shared.global [%0], [%1], 16;" \
                 :: "r"(dst), "l"(src) : "memory")
#define CP_COMMIT() asm volatile("cp.async.commit_group;" ::: "memory")
#define CP_WAIT(n)  asm volatile("cp.async.wait_group %0;" :: "n"(n) : "memory")

#define LDSM4(r, addr) \
    asm volatile("ldmatrix.sync.aligned.m8n8.x4.shared.b16 {%0,%1,%2,%3}, [%4];" \
                 : "=r"((r)[0]), "=r"((r)[1]), "=r"((r)[2]), "=r"((r)[3]) : "r"(addr))
#define LDSM4T(r, addr) \
    asm volatile("ldmatrix.sync.aligned.m8n8.x4.trans.shared.b16 {%0,%1,%2,%3}, [%4];" \
                 : "=r"((r)[0]), "=r"((r)[1]), "=r"((r)[2]), "=r"((r)[3]) : "r"(addr))

#define MMA16816(c, a, b0, b1) \
    asm volatile("mma.sync.aligned.m16n8k16.row.col.f32.f16.f16.f32 " \
                 "{%0,%1,%2,%3}, {%4,%5,%6,%7}, {%8,%9}, {%0,%1,%2,%3};" \
                 : "+f"((c)[0]), "+f"((c)[1]), "+f"((c)[2]), "+f"((c)[3]) \
                 : "r"((a)[0]), "r"((a)[1]), "r"((a)[2]), "r"((a)[3]), \
                   "r"(b0), "r"(b1))

// pack two floats -> fp16x2 (x in low half)
__device__ __forceinline__ uint32_t pack2h(float x, float y) {
    uint32_t d;
    asm("cvt.rn.f16x2.f32 %0, %1, %2;" : "=r"(d) : "f"(y), "f"(x));
    return d;
}
// raw exp2 (single EX2 op)
__device__ __forceinline__ float ex2(float x) {
    float r;
    asm("ex2.approx.f32 %0, %1;" : "=f"(r) : "f"(x));
    return r;
}

#define QSCALE 0.1803368801111137f   // 0.125 * log2(e)
#define LOG2E  1.4426950408889634f

// ---------------------------------------------------------------------------
// prelude (fused, grid 32x32x6):
//  z=0..3: W[K,N] fp32 -> WT[N,K] fp16 (tiled transpose, half2 stores)
//  z=4:    convA (hidden fp32 -> fp16), 4 float4 per thread (full coverage)
//  z=5:    prep (scale/sin/cos), first 256 blocks only
// ---------------------------------------------------------------------------
__global__ __launch_bounds__(256) void prelude(
    const float* __restrict__ Wq, const float* __restrict__ Wk,
    const float* __restrict__ Wv, const float* __restrict__ Wo,
    const float4* __restrict__ hidden,
    const float* __restrict__ phi, const float* __restrict__ mag,
    const float* __restrict__ gamma,
    __half* __restrict__ wt, uint2* __restrict__ ahi,
    float4* __restrict__ prp)
{
    const int z = blockIdx.z;
    if (z < 4) {
        __shared__ float t[32][33];
        const float* W = (z == 0) ? Wq : (z == 1) ? Wk : (z == 2) ? Wv : Wo;
        __half* hz = wt + (size_t)z * D_ * D_;
        int n0 = blockIdx.x * 32, k0 = blockIdx.y * 32;
        int tx = threadIdx.x & 31, ty = threadIdx.x >> 5;
        #pragma unroll
        for (int j = 0; j < 4; j++)
            t[ty + j*8][tx] = W[(size_t)(k0 + ty + j*8) * D_ + n0 + tx];
        __syncthreads();
        int tk = threadIdx.x & 15, tn = threadIdx.x >> 4;
        #pragma unroll
        for (int half_ = 0; half_ < 2; half_++) {
            int n = tn + half_ * 16;
            uint32_t pk = pack2h(t[2*tk][n], t[2*tk+1][n]);
            *(uint32_t*)(hz + (size_t)(n0 + n) * D_ + k0 + 2*tk) = pk;
        }
    } else if (z == 4) {
        int base = (blockIdx.y * 32 + blockIdx.x) * 256 + threadIdx.x;
        #pragma unroll
        for (int it = 0; it < 4; it++) {
            int i = base + it * 262144;
            float4 v = hidden[i];
            uint2 ho;
            ho.x = pack2h(v.x, v.y);
            ho.y = pack2h(v.z, v.w);
            ahi[i] = ho;
        }
    } else {
        int blk = blockIdx.y * 32 + blockIdx.x;
        if (blk >= 256) return;
        int i = blk * 256 + threadIdx.x;          // < 65536
        int h = (i >> 10) & 15;
        float sc = 1.0f + gamma[h] * tanhf(mag[i]);
        float s, c;
        sincosf(phi[i], &s, &c);
        prp[i] = make_float4(sc, s, c, 0.f);
    }
}

// ---------------------------------------------------------------------------
// HMMA fp16 GEMM: 128x128 CTA tile, 256 threads = 8 warps (32x64 tiles),
// 3-stage cp.async pipeline, 2 CTAs/SM, B in [N][K] layout.
// Modes:
//  res == nullptr, z=0:   Q -> bias+scale(+QSCALE fold)+rotate -> fp16 head-major
//  res == nullptr, z=1:   K -> bias+scale+rotate -> fp16 head-major
//  res == nullptr, z=2:   V -> bias -> fp16 head-major
//  res != nullptr:        Wo -> bias + residual -> fp32 row-major
// ---------------------------------------------------------------------------
#define GM 128
#define GN 128
#define KC 64
#define OFF_BHI  16384
#define STAGE    32768
#define NSTG     3
#define GEMM_DYN (NSTG*STAGE)   // 98304

__global__ __launch_bounds__(256, 2) void gemm_hmma(
    const __half* __restrict__ Ahi,
    const __half* __restrict__ WThi,
    const float* __restrict__ bias0, const float* __restrict__ bias1,
    const float* __restrict__ bias2,
    const float4* __restrict__ prp,
    __half* __restrict__ qh, __half* __restrict__ kh,
    __half* __restrict__ vh,
    const float* __restrict__ res, float* __restrict__ xout)
{
    extern __shared__ char smraw[];
    const uint32_t sbase = smem_to_u32(smraw);
    const int tid  = threadIdx.x;
    const int lane = tid & 31, wid = tid >> 5;
    const int wm = wid >> 1, wn = wid & 1;    // 4 x 2 warps of 32x64
    const int bm = blockIdx.y * GM, bn = blockIdx.x * GN;
    const int z  = blockIdx.z;

    const __half* Bh = WThi + (size_t)z * D_ * D_;
    const float* bias = (z == 0) ? bias0 : (z == 1) ? bias1 : bias2;

    const int rr  = tid >> 3;     // 0..31
    const int seg = tid & 7;

    #define LOAD_STAGE(s, kc) do { \
        uint32_t sb_ = sbase + (uint32_t)(s) * STAGE; \
        _Pragma("unroll") \
        for (int h4 = 0; h4 < 4; h4++) { \
            int r_ = rr + h4 * 32; \
            uint32_t sw_ = (uint32_t)r_ * 128 + (uint32_t)((seg ^ (r_ & 7)) << 4); \
            size_t ga_ = (size_t)(bm + r_) * D_ + (kc) + seg * 8; \
            size_t gb_ = (size_t)(bn + r_) * D_ + (kc) + seg * 8; \
            CP16(sb_ + sw_,           Ahi + ga_); \
            CP16(sb_ + OFF_BHI + sw_, Bh + gb_); \
        } \
        CP_COMMIT(); \
    } while (0)

    float c[2][8][4];
    #pragma unroll
    for (int mi = 0; mi < 2; mi++)
        #pragma unroll
        for (int ni = 0; ni < 8; ni++)
            #pragma unroll
            for (int e = 0; e < 4; e++) c[mi][ni][e] = 0.f;

    LOAD_STAGE(0, 0);
    LOAD_STAGE(1, KC);

    const int rAb = wm * 32 + (lane & 15);
    const int rBb = wn * 64 + ((lane >> 4) << 3) + (lane & 7);
    const int sgA = lane >> 4;
    const int sgB = (lane >> 3) & 1;

    int cur = 0;
    for (int ch = 0; ch < 16; ch++) {
        if (ch < 15) CP_WAIT(1);
        else         CP_WAIT(0);
        __syncthreads();
        if (ch < 14) {
            int nxt = cur + 2;
            if (nxt >= 3) nxt -= 3;
            LOAD_STAGE(nxt, (ch + 2) * KC);
        }

        const uint32_t sb = sbase + (uint32_t)cur * STAGE;
        #pragma unroll
        for (int ks = 0; ks < 4; ks++) {
            uint32_t ah[2][4];
            #pragma unroll
            for (int mi = 0; mi < 2; mi++) {
                int rA = rAb + mi * 16;
                uint32_t addr = sb + (uint32_t)rA * 128
                              + (uint32_t)(((ks * 2 + sgA) ^ (rA & 7)) << 4);
                LDSM4(ah[mi], addr);
            }
            #pragma unroll
            for (int np = 0; np < 4; np++) {
                int rB = rBb + np * 16;
                uint32_t addr = sb + OFF_BHI + (uint32_t)rB * 128
                              + (uint32_t)(((ks * 2 + sgB) ^ (rB & 7)) << 4);
                uint32_t bh[4];
                LDSM4(bh, addr);
                #pragma unroll
                for (int hf = 0; hf < 2; hf++) {
                    int ni = np * 2 + hf, rb = hf * 2;
                    #pragma unroll
                    for (int mi = 0; mi < 2; mi++)
                        MMA16816(c[mi][ni], ah[mi], bh[rb], bh[rb + 1]);
                }
            }
        }
        cur++;
        if (cur == 3) cur = 0;
    }

    // ---- epilogue ----
    const int g = lane >> 2, tig = lane & 3;
    if (res) {
        // Wo projection + bias + residual -> fp32 row-major
        #pragma unroll
        for (int mi = 0; mi < 2; mi++) {
            int row0 = bm + wm * 32 + mi * 16 + g;
            #pragma unroll
            for (int ni = 0; ni < 8; ni++) {
                int col = bn + wn * 64 + ni * 8 + tig * 2;
                float2 bv = *(const float2*)(bias + col);
                float2 r0 = *(const float2*)(res + (size_t)row0 * D_ + col);
                float2 r1 = *(const float2*)(res + (size_t)(row0 + 8) * D_ + col);
                *(float2*)(xout + (size_t)row0 * D_ + col) =
                    make_float2(c[mi][ni][0] + bv.x + r0.x, c[mi][ni][1] + bv.y + r0.y);
                *(float2*)(xout + (size_t)(row0 + 8) * D_ + col) =
                    make_float2(c[mi][ni][2] + bv.x + r1.x, c[mi][ni][3] + bv.y + r1.y);
            }
        }
    } else if (z == 2) {
        // V: bias -> fp16 head-major
        #pragma unroll
        for (int mi = 0; mi < 2; mi++) {
            int row0 = bm + wm * 32 + mi * 16 + g;
            int bidx = row0 >> 10, l0 = row0 & 1023;
            #pragma unroll
            for (int ni = 0; ni < 8; ni++) {
                int col = bn + wn * 64 + ni * 8 + tig * 2;
                float2 bv = *(const float2*)(bias + col);
                size_t o0 = (((size_t)bidx * 16 + (col >> 6)) * 1024 + l0) * 64 + (col & 63);
                size_t o1 = o0 + 8 * 64;
                *(uint32_t*)(vh + o0) = pack2h(c[mi][ni][0] + bv.x, c[mi][ni][1] + bv.y);
                *(uint32_t*)(vh + o1) = pack2h(c[mi][ni][2] + bv.x, c[mi][ni][3] + bv.y);
            }
        }
    } else {
        // Q/K: bias + scale + rotate -> fp16 head-major (Q folds QSCALE)
        __half* oh = (z == 0) ? qh : kh;
        const float fs = (z == 0) ? QSCALE : 1.0f;
        const int hh = (bn + wn * 64) >> 6;
        #pragma unroll
        for (int mi = 0; mi < 2; mi++) {
            int row0 = bm + wm * 32 + mi * 16 + g;
            int bidx = row0 >> 10, l0 = row0 & 1023;
            int pidx = (bidx * 16 + hh) * 1024 + l0;
            float4 p0 = prp[pidx];
            float4 p1 = prp[pidx + 8];
            float s0 = p0.x * fs, s1 = p1.x * fs;
            size_t ob = ((size_t)(bidx * 16 + hh) * 1024 + l0) * 64;
            #pragma unroll
            for (int ni = 0; ni < 4; ni++) {
                int d = ni * 8 + tig * 2;
                float2 b1 = *(const float2*)(bias + bn + wn * 64 + d);
                float2 b2 = *(const float2*)(bias + bn + wn * 64 + d + 32);
                // row0
                {
                    float x0 = (c[mi][ni][0]   + b1.x) * s0;
                    float x1 = (c[mi][ni][1]   + b1.y) * s0;
                    float y0 = (c[mi][ni+4][0] + b2.x) * s0;
                    float y1 = (c[mi][ni+4][1] + b2.y) * s0;
                    *(uint32_t*)(oh + ob + d) =
                        pack2h(x0 * p0.z - y0 * p0.y, x1 * p0.z - y1 * p0.y);
                    *(uint32_t*)(oh + ob + d + 32) =
                        pack2h(y0 * p0.z + x0 * p0.y, y1 * p0.z + x1 * p0.y);
                }
                // row0 + 8
                {
                    float x0 = (c[mi][ni][2]   + b1.x) * s1;
                    float x1 = (c[mi][ni][3]   + b1.y) * s1;
                    float y0 = (c[mi][ni+4][2] + b2.x) * s1;
                    float y1 = (c[mi][ni+4][3] + b2.y) * s1;
                    *(uint32_t*)(oh + ob + 512 + d) =
                        pack2h(x0 * p1.z - y0 * p1.y, x1 * p1.z - y1 * p1.y);
                    *(uint32_t*)(oh + ob + 512 + d + 32) =
                        pack2h(y0 * p1.z + x0 * p1.y, y1 * p1.z + x1 * p1.y);
                }
            }
        }
    }
    #undef LOAD_STAGE
}

// ---------------------------------------------------------------------------
// HMMA fp16 flash attention: Q pre-scaled by 0.125*log2e, mask pre-scaled by
// log2e, EX2-based softmax, Q fragments hoisted out of the KV loop.
// ---------------------------------------------------------------------------
#define AT_Q   0
#define AT_STG 16384
#define KVSTG  16384                  // K @0, V @8192
#define AT_MASK (AT_STG + 3*KVSTG)    // 65536
#define ATTN_DYN (AT_MASK + 4096)     // 69632

__global__ __launch_bounds__(256, 2) void attn_hmma(
    const __half* __restrict__ qhi,
    const __half* __restrict__ khi,
    const __half* __restrict__ vhi,
    const float* __restrict__ mask,
    __half* __restrict__ chi)
{
    extern __shared__ char smraw[];
    const uint32_t sb = smem_to_u32(smraw);
    const int tid = threadIdx.x, lane = tid & 31, w = tid >> 5;
    const int qt = blockIdx.x, bh = blockIdx.y;
    const int b = bh >> 4, h = bh & 15;

    // mask: load + pre-scale by log2e (plain st.shared; ordered by syncthreads)
    {
        float4 mv = *(const float4*)(mask + b * 1024 + tid * 4);
        mv.x *= LOG2E; mv.y *= LOG2E; mv.z *= LOG2E; mv.w *= LOG2E;
        *(float4*)(smraw + AT_MASK + tid * 16) = mv;
    }
    #pragma unroll
    for (int it = 0; it < 4; it++) {
        int idx = tid + it * 256, r = idx >> 3, seg = idx & 7;
        size_t g = ((size_t)bh * 1024 + qt * 128 + r) * 64 + seg * 8;
        uint32_t d = sb + (uint32_t)r * 128 + (uint32_t)((seg ^ (r & 7)) << 4);
        CP16(d + AT_Q, qhi + g);
    }
    CP_COMMIT();

    #define LOADKV(s, kt_) do { \
        _Pragma("unroll") \
        for (int it = 0; it < 2; it++) { \
            int idx = tid + it * 256, r = idx >> 3, sg = idx & 7; \
            size_t g = ((size_t)bh * 1024 + (kt_) * 64 + r) * 64 + sg * 8; \
            uint32_t d = sb + AT_STG + (uint32_t)(s) * KVSTG \
                       + (uint32_t)r * 128 + (uint32_t)((sg ^ (r & 7)) << 4); \
            CP16(d,        khi + g); \
            CP16(d + 8192, vhi + g); \
        } \
        CP_COMMIT(); \
    } while (0)

    LOADKV(0, 0);
    LOADKV(1, 1);

    float o[8][4];
    #pragma unroll
    for (int j = 0; j < 8; j++)
        #pragma unroll
        for (int e = 0; e < 4; e++) o[j][e] = 0.f;
    float m0 = -INFINITY, m1 = -INFINITY, l0 = 0.f, l1 = 0.f;

    const int rA = w * 16 + (lane & 15);
    const int rBb = ((lane >> 4) << 3) + (lane & 7);
    const int c2 = (lane & 3) * 2;

    // Q ready after group 0 completes (2 KV groups still pending)
    CP_WAIT(2);
    __syncthreads();
    uint32_t qf[4][4];
    #pragma unroll
    for (int ks = 0; ks < 4; ks++) {
        uint32_t aaddr = sb + AT_Q + (uint32_t)rA * 128
                       + (uint32_t)(((ks * 2 + (lane >> 4)) ^ (rA & 7)) << 4);
        LDSM4(qf[ks], aaddr);
    }

    int cur = 0;
    for (int kt = 0; kt < 16; kt++) {
        if (kt < 15) CP_WAIT(1);
        else         CP_WAIT(0);
        __syncthreads();
        if (kt < 14) {
            int nxt = cur + 2;
            if (nxt >= 3) nxt -= 3;
            LOADKV(nxt, kt + 2);
        }
        const uint32_t kb = sb + AT_STG + (uint32_t)cur * KVSTG;

        float s[8][4];
        #pragma unroll
        for (int j = 0; j < 8; j++)
            #pragma unroll
            for (int e = 0; e < 4; e++) s[j][e] = 0.f;

        #pragma unroll
        for (int ks = 0; ks < 4; ks++) {
            #pragma unroll
            for (int np = 0; np < 4; np++) {
                int rB = np * 16 + rBb;
                uint32_t baddr = kb + (uint32_t)rB * 128
                               + (uint32_t)(((ks * 2 + ((lane >> 3) & 1)) ^ (rB & 7)) << 4);
                uint32_t bhF[4];
                LDSM4(bhF, baddr);
                #pragma unroll
                for (int hf = 0; hf < 2; hf++) {
                    int nt = np * 2 + hf, rb = hf * 2;
                    MMA16816(s[nt], qf[ks], bhF[rb], bhF[rb + 1]);
                }
            }
        }

        // scores are already in log2 domain (Q pre-scaled); add log2e-mask
        float mx0 = -INFINITY, mx1 = -INFINITY;
        #pragma unroll
        for (int j = 0; j < 8; j++) {
            float2 mk = *(float2*)(smraw + AT_MASK + (size_t)(kt * 64 + j * 8 + c2) * 4);
            s[j][0] += mk.x;
            s[j][1] += mk.y;
            s[j][2] += mk.x;
            s[j][3] += mk.y;
            mx0 = fmaxf(mx0, fmaxf(s[j][0], s[j][1]));
            mx1 = fmaxf(mx1, fmaxf(s[j][2], s[j][3]));
        }
        #pragma unroll
        for (int off = 1; off < 4; off <<= 1) {
            mx0 = fmaxf(mx0, __shfl_xor_sync(0xffffffffu, mx0, off));
            mx1 = fmaxf(mx1, __shfl_xor_sync(0xffffffffu, mx1, off));
        }
        float mn0 = fmaxf(m0, mx0), mn1 = fmaxf(m1, mx1);
        float corr0 = ex2(m0 - mn0), corr1 = ex2(m1 - mn1);
        m0 = mn0; m1 = mn1;
        float sum0 = 0.f, sum1 = 0.f;
        #pragma unroll
        for (int j = 0; j < 8; j++) {
            s[j][0] = ex2(s[j][0] - m0);
            s[j][1] = ex2(s[j][1] - m0);
            s[j][2] = ex2(s[j][2] - m1);
            s[j][3] = ex2(s[j][3] - m1);
            sum0 += s[j][0] + s[j][1];
            sum1 += s[j][2] + s[j][3];
        }
        #pragma unroll
        for (int off = 1; off < 4; off <<= 1) {
            sum0 += __shfl_xor_sync(0xffffffffu, sum0, off);
            sum1 += __shfl_xor_sync(0xffffffffu, sum1, off);
        }
        l0 = l0 * corr0 + sum0;
        l1 = l1 * corr1 + sum1;
        #pragma unroll
        for (int j = 0; j < 8; j++) {
            o[j][0] *= corr0; o[j][1] *= corr0;
            o[j][2] *= corr1; o[j][3] *= corr1;
        }

        #pragma unroll
        for (int kg = 0; kg < 4; kg++) {
            uint32_t ph[4];
            ph[0] = pack2h(s[2*kg][0],   s[2*kg][1]);
            ph[1] = pack2h(s[2*kg][2],   s[2*kg][3]);
            ph[2] = pack2h(s[2*kg+1][0], s[2*kg+1][1]);
            ph[3] = pack2h(s[2*kg+1][2], s[2*kg+1][3]);
            int rV = kg * 16 + (lane & 15);
            #pragma unroll
            for (int np = 0; np < 4; np++) {
                uint32_t vaddr = kb + 8192 + (uint32_t)rV * 128
                               + (uint32_t)(((np * 2 + (lane >> 4)) ^ (rV & 7)) << 4);
                uint32_t vhF[4];
                LDSM4T(vhF, vaddr);
                #pragma unroll
                for (int hf = 0; hf < 2; hf++) {
                    int nt = np * 2 + hf, rb = hf * 2;
                    MMA16816(o[nt], ph, vhF[rb], vhF[rb + 1]);
                }
            }
        }

        cur++;
        if (cur == 3) cur = 0;
    }

    float i0 = 1.0f / l0, i1 = 1.0f / l1;
    size_t row0 = (size_t)b * 1024 + qt * 128 + w * 16 + (lane >> 2);
    #pragma unroll
    for (int j = 0; j < 8; j++) {
        int col = h * 64 + j * 8 + c2;
        *(uint32_t*)(chi + row0 * D_ + col)       = pack2h(o[j][0] * i0, o[j][1] * i0);
        *(uint32_t*)(chi + (row0 + 8) * D_ + col) = pack2h(o[j][2] * i1, o[j][3] * i1);
    }
    #undef LOADKV
}

// ---------------------------------------------------------------------------
// LayerNorm over last dim (1024).
// ---------------------------------------------------------------------------
__global__ __launch_bounds__(256) void lnorm(
    const float* __restrict__ X, const float* __restrict__ hsc,
    const float* __restrict__ hbi, float* __restrict__ out)
{
    int row = blockIdx.x;
    int c4 = threadIdx.x * 4;
    const float* x = X + (size_t)row * D_;
    float4 v = *(const float4*)(x + c4);
    float sum = v.x + v.y + v.z + v.w;
    float sq  = v.x*v.x + v.y*v.y + v.z*v.z + v.w*v.w;
    #pragma unroll
    for (int off = 16; off > 0; off >>= 1) {
        sum += __shfl_xor_sync(0xffffffffu, sum, off);
        sq  += __shfl_xor_sync(0xffffffffu, sq,  off);
    }
    __shared__ float rs[8], rq[8];
    int warp = threadIdx.x >> 5;
    if ((threadIdx.x & 31) == 0) { rs[warp] = sum; rq[warp] = sq; }
    __syncthreads();
    float tot = 0.f, totq = 0.f;
    #pragma unroll
    for (int wv = 0; wv < 8; wv++) { tot += rs[wv]; totq += rq[wv]; }
    float mu  = tot  * (1.0f / 1024.0f);
    float var = totq * (1.0f / 1024.0f) - mu * mu;
    float inv = rsqrtf(var + 1e-12f);
    float4 sc = *(const float4*)(hsc + c4);
    float4 bi = *(const float4*)(hbi + c4);
    float4 oo;
    oo.x = (v.x - mu) * inv * sc.x + bi.x;
    oo.y = (v.y - mu) * inv * sc.y + bi.y;
    oo.z = (v.z - mu) * inv * sc.z + bi.z;
    oo.w = (v.w - mu) * inv * sc.w + bi.w;
    *(float4*)&out[(size_t)row * D_ + c4] = oo;
}

// ---------------------------------------------------------------------------
extern "C" void kernel_launch(void* const* d_in, const int* in_sizes, int n_in,
                              void* d_out, int out_size)
{
    const float* hidden = (const float*)d_in[0];
    const float* mask   = (const float*)d_in[1];
    const float* phi    = (const float*)d_in[2];
    const float* mag    = (const float*)d_in[3];
    const float* Wq     = (const float*)d_in[4];
    const float* bq     = (const float*)d_in[5];
    const float* Wk     = (const float*)d_in[6];
    const float* bk     = (const float*)d_in[7];
    const float* Wv     = (const float*)d_in[8];
    const float* bv     = (const float*)d_in[9];
    const float* gamma  = (const float*)d_in[10];
    const float* Wo     = (const float*)d_in[11];
    const float* bo     = (const float*)d_in[12];
    const float* lns    = (const float*)d_in[13];
    const float* lnb    = (const float*)d_in[14];
    float* out = (float*)d_out;

    float *x;
    float4* prp;
    __half *ahi, *wthi, *qhi, *khi, *vhi;
    cudaGetSymbolAddress((void**)&x,    g_x);
    cudaGetSymbolAddress((void**)&prp,  g_prep);
    cudaGetSymbolAddress((void**)&ahi,  g_ahi);
    cudaGetSymbolAddress((void**)&wthi, g_wthi);
    cudaGetSymbolAddress((void**)&qhi,  g_qhi);
    cudaGetSymbolAddress((void**)&khi,  g_khi);
    cudaGetSymbolAddress((void**)&vhi,  g_vhi);

    cudaFuncSetAttribute(gemm_hmma, cudaFuncAttributeMaxDynamicSharedMemorySize, GEMM_DYN);
    cudaFuncSetAttribute(attn_hmma, cudaFuncAttributeMaxDynamicSharedMemorySize, ATTN_DYN);

    const int DD = D_ * D_;

    // fused prelude: z=0..3 convW transpose, z=4 convA, z=5 prep
    prelude<<<dim3(32, 32, 6), 256>>>(
        Wq, Wk, Wv, Wo, (const float4*)hidden, phi, mag, gamma,
        wthi, (uint2*)ahi, prp);

    // QKV fused (z: 0=Q rot scaled, 1=K rot, 2=V), fp16 head-major outputs
    gemm_hmma<<<dim3(D_ / GN, M_TOT / GM, 3), 256, GEMM_DYN>>>(
        ahi, wthi, bq, bk, bv, prp, qhi, khi, vhi, nullptr, nullptr);

    attn_hmma<<<dim3(L_ / 128, B_ * H_), 256, ATTN_DYN>>>(
        qhi, khi, vhi, mask, ahi);

    // Wo projection + residual
    gemm_hmma<<<dim3(D_ / GN, M_TOT / GM, 1), 256, GEMM_DYN>>>(
        ahi, wthi + 3*DD, bo, bo, bo, prp,
        nullptr, nullptr, nullptr, hidden, x);

    lnorm<<<M_TOT, 256>>>(x, lns, lnb, out);
}

// round 16
// speedup vs baseline: 1.5365x; 1.0288x over previous
#include <cuda_runtime.h>
#include <cuda_fp16.h>
#include <math.h>
#include <stdint.h>

#define B_  4
#define L_  1024
#define D_  1024
#define H_  16
#define HD_ 64
#define M_TOT (B_*L_)   // 4096

// ---------------------------------------------------------------------------
// Scratch
// ---------------------------------------------------------------------------
__device__ float g_x[M_TOT * D_];
__device__ float4 g_prep[B_ * H_ * L_];     // (sc, sin, cos, 0) per (bh,l)
__device__ __half g_ahi[M_TOT * D_];        // activations / ctx fp16
__device__ __half g_wthi[4 * D_ * D_];      // W^T [N][K] fp16 (q,k,v,o)
__device__ __half g_qhi[M_TOT * D_];        // rotated Q fp16 (pre-scaled), head-major
__device__ __half g_khi[M_TOT * D_];        // rotated K fp16, head-major
__device__ __half g_vhi[M_TOT * D_];        // V fp16, head-major

// ---------------------------------------------------------------------------
// Helpers
// ---------------------------------------------------------------------------
__device__ __forceinline__ uint32_t smem_to_u32(const void* p) {
    uint32_t a;
    asm("{ .reg .u64 t; cvta.to.shared.u64 t, %1; cvt.u32.u64 %0, t; }"
        : "=r"(a) : "l"(p));
    return a;
}

#define CP16(dst, src) \
    asm volatile("cp.async.cg.shared.global [%0], [%1], 16;" \
                 :: "r"(dst), "l"(src) : "memory")
#define CP_COMMIT() asm volatile("cp.async.commit_group;" ::: "memory")
#define CP_WAIT(n)  asm volatile("cp.async.wait_group %0;" :: "n"(n) : "memory")

#define LDSM4(r, addr) \
    asm volatile("ldmatrix.sync.aligned.m8n8.x4.shared.b16 {%0,%1,%2,%3}, [%4];" \
                 : "=r"((r)[0]), "=r"((r)[1]), "=r"((r)[2]), "=r"((r)[3]) : "r"(addr))
#define LDSM4T(r, addr) \
    asm volatile("ldmatrix.sync.aligned.m8n8.x4.trans.shared.b16 {%0,%1,%2,%3}, [%4];" \
                 : "=r"((r)[0]), "=r"((r)[1]), "=r"((r)[2]), "=r"((r)[3]) : "r"(addr))

#define MMA16816(c, a, b0, b1) \
    asm volatile("mma.sync.aligned.m16n8k16.row.col.f32.f16.f16.f32 " \
                 "{%0,%1,%2,%3}, {%4,%5,%6,%7}, {%8,%9}, {%0,%1,%2,%3};" \
                 : "+f"((c)[0]), "+f"((c)[1]), "+f"((c)[2]), "+f"((c)[3]) \
                 : "r"((a)[0]), "r"((a)[1]), "r"((a)[2]), "r"((a)[3]), \
                   "r"(b0), "r"(b1))

// pack two floats -> fp16x2 (x in low half)
__device__ __forceinline__ uint32_t pack2h(float x, float y) {
    uint32_t d;
    asm("cvt.rn.f16x2.f32 %0, %1, %2;" : "=r"(d) : "f"(y), "f"(x));
    return d;
}
// raw exp2 (single EX2 op)
__device__ __forceinline__ float ex2(float x) {
    float r;
    asm("ex2.approx.f32 %0, %1;" : "=f"(r) : "f"(x));
    return r;
}

#define QSCALE 0.1803368801111137f   // 0.125 * log2(e)
#define LOG2E  1.4426950408889634f

// ---------------------------------------------------------------------------
// prelude (fused, grid 32x32x6):
//  z=0..3: W[K,N] fp32 -> WT[N,K] fp16 (tiled transpose, half2 stores)
//  z=4:    convA (hidden fp32 -> fp16), 4 float4 per thread (full coverage)
//  z=5:    prep (scale/sin/cos), first 256 blocks only
// ---------------------------------------------------------------------------
__global__ __launch_bounds__(256) void prelude(
    const float* __restrict__ Wq, const float* __restrict__ Wk,
    const float* __restrict__ Wv, const float* __restrict__ Wo,
    const float4* __restrict__ hidden,
    const float* __restrict__ phi, const float* __restrict__ mag,
    const float* __restrict__ gamma,
    __half* __restrict__ wt, uint2* __restrict__ ahi,
    float4* __restrict__ prp)
{
    const int z = blockIdx.z;
    if (z < 4) {
        __shared__ float t[32][33];
        const float* W = (z == 0) ? Wq : (z == 1) ? Wk : (z == 2) ? Wv : Wo;
        __half* hz = wt + (size_t)z * D_ * D_;
        int n0 = blockIdx.x * 32, k0 = blockIdx.y * 32;
        int tx = threadIdx.x & 31, ty = threadIdx.x >> 5;
        #pragma unroll
        for (int j = 0; j < 4; j++)
            t[ty + j*8][tx] = W[(size_t)(k0 + ty + j*8) * D_ + n0 + tx];
        __syncthreads();
        int tk = threadIdx.x & 15, tn = threadIdx.x >> 4;
        #pragma unroll
        for (int half_ = 0; half_ < 2; half_++) {
            int n = tn + half_ * 16;
            uint32_t pk = pack2h(t[2*tk][n], t[2*tk+1][n]);
            *(uint32_t*)(hz + (size_t)(n0 + n) * D_ + k0 + 2*tk) = pk;
        }
    } else if (z == 4) {
        int base = (blockIdx.y * 32 + blockIdx.x) * 256 + threadIdx.x;
        #pragma unroll
        for (int it = 0; it < 4; it++) {
            int i = base + it * 262144;
            float4 v = hidden[i];
            uint2 ho;
            ho.x = pack2h(v.x, v.y);
            ho.y = pack2h(v.z, v.w);
            ahi[i] = ho;
        }
    } else {
        int blk = blockIdx.y * 32 + blockIdx.x;
        if (blk >= 256) return;
        int i = blk * 256 + threadIdx.x;          // < 65536
        int h = (i >> 10) & 15;
        float sc = 1.0f + gamma[h] * tanhf(mag[i]);
        float s, c;
        sincosf(phi[i], &s, &c);
        prp[i] = make_float4(sc, s, c, 0.f);
    }
}

// ---------------------------------------------------------------------------
// HMMA fp16 GEMM: 128x128 CTA tile, 256 threads = 8 warps (32x64 tiles),
// 3-stage cp.async pipeline, 2 CTAs/SM, B in [N][K] layout.
// Modes:
//  res == nullptr, z=0:   Q -> bias+scale(+QSCALE fold)+rotate -> fp16 head-major
//  res == nullptr, z=1:   K -> bias+scale+rotate -> fp16 head-major
//  res == nullptr, z=2:   V -> bias -> fp16 head-major
//  res != nullptr:        Wo -> bias + residual -> fp32 row-major
// ---------------------------------------------------------------------------
#define GM 128
#define GN 128
#define KC 64
#define OFF_BHI  16384
#define STAGE    32768
#define NSTG     3
#define GEMM_DYN (NSTG*STAGE)   // 98304

__global__ __launch_bounds__(256, 2) void gemm_hmma(
    const __half* __restrict__ Ahi,
    const __half* __restrict__ WThi,
    const float* __restrict__ bias0, const float* __restrict__ bias1,
    const float* __restrict__ bias2,
    const float4* __restrict__ prp,
    __half* __restrict__ qh, __half* __restrict__ kh,
    __half* __restrict__ vh,
    const float* __restrict__ res, float* __restrict__ xout)
{
    extern __shared__ char smraw[];
    const uint32_t sbase = smem_to_u32(smraw);
    const int tid  = threadIdx.x;
    const int lane = tid & 31, wid = tid >> 5;
    const int wm = wid >> 1, wn = wid & 1;    // 4 x 2 warps of 32x64
    const int bm = blockIdx.y * GM, bn = blockIdx.x * GN;
    const int z  = blockIdx.z;

    const __half* Bh = WThi + (size_t)z * D_ * D_;
    const float* bias = (z == 0) ? bias0 : (z == 1) ? bias1 : bias2;

    const int rr  = tid >> 3;     // 0..31
    const int seg = tid & 7;

    #define LOAD_STAGE(s, kc) do { \
        uint32_t sb_ = sbase + (uint32_t)(s) * STAGE; \
        _Pragma("unroll") \
        for (int h4 = 0; h4 < 4; h4++) { \
            int r_ = rr + h4 * 32; \
            uint32_t sw_ = (uint32_t)r_ * 128 + (uint32_t)((seg ^ (r_ & 7)) << 4); \
            size_t ga_ = (size_t)(bm + r_) * D_ + (kc) + seg * 8; \
            size_t gb_ = (size_t)(bn + r_) * D_ + (kc) + seg * 8; \
            CP16(sb_ + sw_,           Ahi + ga_); \
            CP16(sb_ + OFF_BHI + sw_, Bh + gb_); \
        } \
        CP_COMMIT(); \
    } while (0)

    float c[2][8][4];
    #pragma unroll
    for (int mi = 0; mi < 2; mi++)
        #pragma unroll
        for (int ni = 0; ni < 8; ni++)
            #pragma unroll
            for (int e = 0; e < 4; e++) c[mi][ni][e] = 0.f;

    LOAD_STAGE(0, 0);
    LOAD_STAGE(1, KC);

    const int rAb = wm * 32 + (lane & 15);
    const int rBb = wn * 64 + ((lane >> 4) << 3) + (lane & 7);
    const int sgA = lane >> 4;
    const int sgB = (lane >> 3) & 1;

    int cur = 0;
    for (int ch = 0; ch < 16; ch++) {
        if (ch < 15) CP_WAIT(1);
        else         CP_WAIT(0);
        __syncthreads();
        if (ch < 14) {
            int nxt = cur + 2;
            if (nxt >= 3) nxt -= 3;
            LOAD_STAGE(nxt, (ch + 2) * KC);
        }

        const uint32_t sb = sbase + (uint32_t)cur * STAGE;
        #pragma unroll
        for (int ks = 0; ks < 4; ks++) {
            uint32_t ah[2][4];
            #pragma unroll
            for (int mi = 0; mi < 2; mi++) {
                int rA = rAb + mi * 16;
                uint32_t addr = sb + (uint32_t)rA * 128
                              + (uint32_t)(((ks * 2 + sgA) ^ (rA & 7)) << 4);
                LDSM4(ah[mi], addr);
            }
            #pragma unroll
            for (int np = 0; np < 4; np++) {
                int rB = rBb + np * 16;
                uint32_t addr = sb + OFF_BHI + (uint32_t)rB * 128
                              + (uint32_t)(((ks * 2 + sgB) ^ (rB & 7)) << 4);
                uint32_t bh[4];
                LDSM4(bh, addr);
                #pragma unroll
                for (int hf = 0; hf < 2; hf++) {
                    int ni = np * 2 + hf, rb = hf * 2;
                    #pragma unroll
                    for (int mi = 0; mi < 2; mi++)
                        MMA16816(c[mi][ni], ah[mi], bh[rb], bh[rb + 1]);
                }
            }
        }
        cur++;
        if (cur == 3) cur = 0;
    }

    // ---- epilogue ----
    const int g = lane >> 2, tig = lane & 3;
    if (res) {
        // Wo projection + bias + residual -> fp32 row-major
        #pragma unroll
        for (int mi = 0; mi < 2; mi++) {
            int row0 = bm + wm * 32 + mi * 16 + g;
            #pragma unroll
            for (int ni = 0; ni < 8; ni++) {
                int col = bn + wn * 64 + ni * 8 + tig * 2;
                float2 bv = *(const float2*)(bias + col);
                float2 r0 = *(const float2*)(res + (size_t)row0 * D_ + col);
                float2 r1 = *(const float2*)(res + (size_t)(row0 + 8) * D_ + col);
                *(float2*)(xout + (size_t)row0 * D_ + col) =
                    make_float2(c[mi][ni][0] + bv.x + r0.x, c[mi][ni][1] + bv.y + r0.y);
                *(float2*)(xout + (size_t)(row0 + 8) * D_ + col) =
                    make_float2(c[mi][ni][2] + bv.x + r1.x, c[mi][ni][3] + bv.y + r1.y);
            }
        }
    } else if (z == 2) {
        // V: bias -> fp16 head-major
        #pragma unroll
        for (int mi = 0; mi < 2; mi++) {
            int row0 = bm + wm * 32 + mi * 16 + g;
            int bidx = row0 >> 10, l0 = row0 & 1023;
            #pragma unroll
            for (int ni = 0; ni < 8; ni++) {
                int col = bn + wn * 64 + ni * 8 + tig * 2;
                float2 bv = *(const float2*)(bias + col);
                size_t o0 = (((size_t)bidx * 16 + (col >> 6)) * 1024 + l0) * 64 + (col & 63);
                size_t o1 = o0 + 8 * 64;
                *(uint32_t*)(vh + o0) = pack2h(c[mi][ni][0] + bv.x, c[mi][ni][1] + bv.y);
                *(uint32_t*)(vh + o1) = pack2h(c[mi][ni][2] + bv.x, c[mi][ni][3] + bv.y);
            }
        }
    } else {
        // Q/K: bias + scale + rotate -> fp16 head-major (Q folds QSCALE)
        __half* oh = (z == 0) ? qh : kh;
        const float fs = (z == 0) ? QSCALE : 1.0f;
        const int hh = (bn + wn * 64) >> 6;
        #pragma unroll
        for (int mi = 0; mi < 2; mi++) {
            int row0 = bm + wm * 32 + mi * 16 + g;
            int bidx = row0 >> 10, l0 = row0 & 1023;
            int pidx = (bidx * 16 + hh) * 1024 + l0;
            float4 p0 = prp[pidx];
            float4 p1 = prp[pidx + 8];
            float s0 = p0.x * fs, s1 = p1.x * fs;
            size_t ob = ((size_t)(bidx * 16 + hh) * 1024 + l0) * 64;
            #pragma unroll
            for (int ni = 0; ni < 4; ni++) {
                int d = ni * 8 + tig * 2;
                float2 b1 = *(const float2*)(bias + bn + wn * 64 + d);
                float2 b2 = *(const float2*)(bias + bn + wn * 64 + d + 32);
                // row0
                {
                    float x0 = (c[mi][ni][0]   + b1.x) * s0;
                    float x1 = (c[mi][ni][1]   + b1.y) * s0;
                    float y0 = (c[mi][ni+4][0] + b2.x) * s0;
                    float y1 = (c[mi][ni+4][1] + b2.y) * s0;
                    *(uint32_t*)(oh + ob + d) =
                        pack2h(x0 * p0.z - y0 * p0.y, x1 * p0.z - y1 * p0.y);
                    *(uint32_t*)(oh + ob + d + 32) =
                        pack2h(y0 * p0.z + x0 * p0.y, y1 * p0.z + x1 * p0.y);
                }
                // row0 + 8
                {
                    float x0 = (c[mi][ni][2]   + b1.x) * s1;
                    float x1 = (c[mi][ni][3]   + b1.y) * s1;
                    float y0 = (c[mi][ni+4][2] + b2.x) * s1;
                    float y1 = (c[mi][ni+4][3] + b2.y) * s1;
                    *(uint32_t*)(oh + ob + 512 + d) =
                        pack2h(x0 * p1.z - y0 * p1.y, x1 * p1.z - y1 * p1.y);
                    *(uint32_t*)(oh + ob + 512 + d + 32) =
                        pack2h(y0 * p1.z + x0 * p1.y, y1 * p1.z + x1 * p1.y);
                }
            }
        }
    }
    #undef LOAD_STAGE
}

// ---------------------------------------------------------------------------
// HMMA fp16 flash attention: 64-row q-tiles, 128 threads = 4 warps x 16 rows,
// 3 CTAs/SM for wave packing. Q pre-scaled, EX2 softmax, Q frags hoisted.
// Smem: Q 8K @0, 3 KV stages 16K each @8192, mask 4K @57344. Total 61440.
// ---------------------------------------------------------------------------
#define AT_Q   0
#define AT_STG 8192
#define KVSTG  16384                  // K @0, V @8192
#define AT_MASK (AT_STG + 3*KVSTG)    // 57344
#define ATTN_DYN (AT_MASK + 4096)     // 61440

__global__ __launch_bounds__(128, 3) void attn_hmma(
    const __half* __restrict__ qhi,
    const __half* __restrict__ khi,
    const __half* __restrict__ vhi,
    const float* __restrict__ mask,
    __half* __restrict__ chi)
{
    extern __shared__ char smraw[];
    const uint32_t sb = smem_to_u32(smraw);
    const int tid = threadIdx.x, lane = tid & 31, w = tid >> 5;
    const int qt = blockIdx.x, bh = blockIdx.y;
    const int b = bh >> 4, h = bh & 15;

    // mask: load + pre-scale by log2e (plain st.shared; ordered by syncthreads)
    #pragma unroll
    for (int it = 0; it < 2; it++) {
        float4 mv = *(const float4*)(mask + b * 1024 + tid * 4 + it * 512);
        mv.x *= LOG2E; mv.y *= LOG2E; mv.z *= LOG2E; mv.w *= LOG2E;
        *(float4*)(smraw + AT_MASK + tid * 16 + it * 2048) = mv;
    }
    // Q tile: 64 rows x 8 segs = 512 CP16; 128 threads x 4
    #pragma unroll
    for (int it = 0; it < 4; it++) {
        int idx = tid + it * 128, r = idx >> 3, seg = idx & 7;
        size_t g = ((size_t)bh * 1024 + qt * 64 + r) * 64 + seg * 8;
        uint32_t d = sb + (uint32_t)r * 128 + (uint32_t)((seg ^ (r & 7)) << 4);
        CP16(d + AT_Q, qhi + g);
    }
    CP_COMMIT();

    #define LOADKV(s, kt_) do { \
        _Pragma("unroll") \
        for (int it = 0; it < 4; it++) { \
            int idx = tid + it * 128, r = idx >> 3, sg = idx & 7; \
            size_t g = ((size_t)bh * 1024 + (kt_) * 64 + r) * 64 + sg * 8; \
            uint32_t d = sb + AT_STG + (uint32_t)(s) * KVSTG \
                       + (uint32_t)r * 128 + (uint32_t)((sg ^ (r & 7)) << 4); \
            CP16(d,        khi + g); \
            CP16(d + 8192, vhi + g); \
        } \
        CP_COMMIT(); \
    } while (0)

    LOADKV(0, 0);
    LOADKV(1, 1);

    float o[8][4];
    #pragma unroll
    for (int j = 0; j < 8; j++)
        #pragma unroll
        for (int e = 0; e < 4; e++) o[j][e] = 0.f;
    float m0 = -INFINITY, m1 = -INFINITY, l0 = 0.f, l1 = 0.f;

    const int rA = w * 16 + (lane & 15);
    const int rBb = ((lane >> 4) << 3) + (lane & 7);
    const int c2 = (lane & 3) * 2;

    // Q ready after group 0 completes (2 KV groups still pending)
    CP_WAIT(2);
    __syncthreads();
    uint32_t qf[4][4];
    #pragma unroll
    for (int ks = 0; ks < 4; ks++) {
        uint32_t aaddr = sb + AT_Q + (uint32_t)rA * 128
                       + (uint32_t)(((ks * 2 + (lane >> 4)) ^ (rA & 7)) << 4);
        LDSM4(qf[ks], aaddr);
    }

    int cur = 0;
    for (int kt = 0; kt < 16; kt++) {
        if (kt < 15) CP_WAIT(1);
        else         CP_WAIT(0);
        __syncthreads();
        if (kt < 14) {
            int nxt = cur + 2;
            if (nxt >= 3) nxt -= 3;
            LOADKV(nxt, kt + 2);
        }
        const uint32_t kb = sb + AT_STG + (uint32_t)cur * KVSTG;

        float s[8][4];
        #pragma unroll
        for (int j = 0; j < 8; j++)
            #pragma unroll
            for (int e = 0; e < 4; e++) s[j][e] = 0.f;

        #pragma unroll
        for (int ks = 0; ks < 4; ks++) {
            #pragma unroll
            for (int np = 0; np < 4; np++) {
                int rB = np * 16 + rBb;
                uint32_t baddr = kb + (uint32_t)rB * 128
                               + (uint32_t)(((ks * 2 + ((lane >> 3) & 1)) ^ (rB & 7)) << 4);
                uint32_t bhF[4];
                LDSM4(bhF, baddr);
                #pragma unroll
                for (int hf = 0; hf < 2; hf++) {
                    int nt = np * 2 + hf, rb = hf * 2;
                    MMA16816(s[nt], qf[ks], bhF[rb], bhF[rb + 1]);
                }
            }
        }

        // scores in log2 domain; add log2e-scaled mask
        float mx0 = -INFINITY, mx1 = -INFINITY;
        #pragma unroll
        for (int j = 0; j < 8; j++) {
            float2 mk = *(float2*)(smraw + AT_MASK + (size_t)(kt * 64 + j * 8 + c2) * 4);
            s[j][0] += mk.x;
            s[j][1] += mk.y;
            s[j][2] += mk.x;
            s[j][3] += mk.y;
            mx0 = fmaxf(mx0, fmaxf(s[j][0], s[j][1]));
            mx1 = fmaxf(mx1, fmaxf(s[j][2], s[j][3]));
        }
        #pragma unroll
        for (int off = 1; off < 4; off <<= 1) {
            mx0 = fmaxf(mx0, __shfl_xor_sync(0xffffffffu, mx0, off));
            mx1 = fmaxf(mx1, __shfl_xor_sync(0xffffffffu, mx1, off));
        }
        float mn0 = fmaxf(m0, mx0), mn1 = fmaxf(m1, mx1);
        float corr0 = ex2(m0 - mn0), corr1 = ex2(m1 - mn1);
        m0 = mn0; m1 = mn1;
        float sum0 = 0.f, sum1 = 0.f;
        #pragma unroll
        for (int j = 0; j < 8; j++) {
            s[j][0] = ex2(s[j][0] - m0);
            s[j][1] = ex2(s[j][1] - m0);
            s[j][2] = ex2(s[j][2] - m1);
            s[j][3] = ex2(s[j][3] - m1);
            sum0 += s[j][0] + s[j][1];
            sum1 += s[j][2] + s[j][3];
        }
        #pragma unroll
        for (int off = 1; off < 4; off <<= 1) {
            sum0 += __shfl_xor_sync(0xffffffffu, sum0, off);
            sum1 += __shfl_xor_sync(0xffffffffu, sum1, off);
        }
        l0 = l0 * corr0 + sum0;
        l1 = l1 * corr1 + sum1;
        #pragma unroll
        for (int j = 0; j < 8; j++) {
            o[j][0] *= corr0; o[j][1] *= corr0;
            o[j][2] *= corr1; o[j][3] *= corr1;
        }

        #pragma unroll
        for (int kg = 0; kg < 4; kg++) {
            uint32_t ph[4];
            ph[0] = pack2h(s[2*kg][0],   s[2*kg][1]);
            ph[1] = pack2h(s[2*kg][2],   s[2*kg][3]);
            ph[2] = pack2h(s[2*kg+1][0], s[2*kg+1][1]);
            ph[3] = pack2h(s[2*kg+1][2], s[2*kg+1][3]);
            int rV = kg * 16 + (lane & 15);
            #pragma unroll
            for (int np = 0; np < 4; np++) {
                uint32_t vaddr = kb + 8192 + (uint32_t)rV * 128
                               + (uint32_t)(((np * 2 + (lane >> 4)) ^ (rV & 7)) << 4);
                uint32_t vhF[4];
                LDSM4T(vhF, vaddr);
                #pragma unroll
                for (int hf = 0; hf < 2; hf++) {
                    int nt = np * 2 + hf, rb = hf * 2;
                    MMA16816(o[nt], ph, vhF[rb], vhF[rb + 1]);
                }
            }
        }

        cur++;
        if (cur == 3) cur = 0;
    }

    float i0 = 1.0f / l0, i1 = 1.0f / l1;
    size_t row0 = (size_t)b * 1024 + qt * 64 + w * 16 + (lane >> 2);
    #pragma unroll
    for (int j = 0; j < 8; j++) {
        int col = h * 64 + j * 8 + c2;
        *(uint32_t*)(chi + row0 * D_ + col)       = pack2h(o[j][0] * i0, o[j][1] * i0);
        *(uint32_t*)(chi + (row0 + 8) * D_ + col) = pack2h(o[j][2] * i1, o[j][3] * i1);
    }
    #undef LOADKV
}

// ---------------------------------------------------------------------------
// LayerNorm over last dim (1024).
// ---------------------------------------------------------------------------
__global__ __launch_bounds__(256) void lnorm(
    const float* __restrict__ X, const float* __restrict__ hsc,
    const float* __restrict__ hbi, float* __restrict__ out)
{
    int row = blockIdx.x;
    int c4 = threadIdx.x * 4;
    const float* x = X + (size_t)row * D_;
    float4 v = *(const float4*)(x + c4);
    float sum = v.x + v.y + v.z + v.w;
    float sq  = v.x*v.x + v.y*v.y + v.z*v.z + v.w*v.w;
    #pragma unroll
    for (int off = 16; off > 0; off >>= 1) {
        sum += __shfl_xor_sync(0xffffffffu, sum, off);
        sq  += __shfl_xor_sync(0xffffffffu, sq,  off);
    }
    __shared__ float rs[8], rq[8];
    int warp = threadIdx.x >> 5;
    if ((threadIdx.x & 31) == 0) { rs[warp] = sum; rq[warp] = sq; }
    __syncthreads();
    float tot = 0.f, totq = 0.f;
    #pragma unroll
    for (int wv = 0; wv < 8; wv++) { tot += rs[wv]; totq += rq[wv]; }
    float mu  = tot  * (1.0f / 1024.0f);
    float var = totq * (1.0f / 1024.0f) - mu * mu;
    float inv = rsqrtf(var + 1e-12f);
    float4 sc = *(const float4*)(hsc + c4);
    float4 bi = *(const float4*)(hbi + c4);
    float4 oo;
    oo.x = (v.x - mu) * inv * sc.x + bi.x;
    oo.y = (v.y - mu) * inv * sc.y + bi.y;
    oo.z = (v.z - mu) * inv * sc.z + bi.z;
    oo.w = (v.w - mu) * inv * sc.w + bi.w;
    *(float4*)&out[(size_t)row * D_ + c4] = oo;
}

// ---------------------------------------------------------------------------
extern "C" void kernel_launch(void* const* d_in, const int* in_sizes, int n_in,
                              void* d_out, int out_size)
{
    const float* hidden = (const float*)d_in[0];
    const float* mask   = (const float*)d_in[1];
    const float* phi    = (const float*)d_in[2];
    const float* mag    = (const float*)d_in[3];
    const float* Wq     = (const float*)d_in[4];
    const float* bq     = (const float*)d_in[5];
    const float* Wk     = (const float*)d_in[6];
    const float* bk     = (const float*)d_in[7];
    const float* Wv     = (const float*)d_in[8];
    const float* bv     = (const float*)d_in[9];
    const float* gamma  = (const float*)d_in[10];
    const float* Wo     = (const float*)d_in[11];
    const float* bo     = (const float*)d_in[12];
    const float* lns    = (const float*)d_in[13];
    const float* lnb    = (const float*)d_in[14];
    float* out = (float*)d_out;

    float *x;
    float4* prp;
    __half *ahi, *wthi, *qhi, *khi, *vhi;
    cudaGetSymbolAddress((void**)&x,    g_x);
    cudaGetSymbolAddress((void**)&prp,  g_prep);
    cudaGetSymbolAddress((void**)&ahi,  g_ahi);
    cudaGetSymbolAddress((void**)&wthi, g_wthi);
    cudaGetSymbolAddress((void**)&qhi,  g_qhi);
    cudaGetSymbolAddress((void**)&khi,  g_khi);
    cudaGetSymbolAddress((void**)&vhi,  g_vhi);

    cudaFuncSetAttribute(gemm_hmma, cudaFuncAttributeMaxDynamicSharedMemorySize, GEMM_DYN);
    cudaFuncSetAttribute(attn_hmma, cudaFuncAttributeMaxDynamicSharedMemorySize, ATTN_DYN);

    const int DD = D_ * D_;

    // fused prelude: z=0..3 convW transpose, z=4 convA, z=5 prep
    prelude<<<dim3(32, 32, 6), 256>>>(
        Wq, Wk, Wv, Wo, (const float4*)hidden, phi, mag, gamma,
        wthi, (uint2*)ahi, prp);

    // QKV fused (z: 0=Q rot scaled, 1=K rot, 2=V), fp16 head-major outputs
    gemm_hmma<<<dim3(D_ / GN, M_TOT / GM, 3), 256, GEMM_DYN>>>(
        ahi, wthi, bq, bk, bv, prp, qhi, khi, vhi, nullptr, nullptr);

    attn_hmma<<<dim3(L_ / 64, B_ * H_), 128, ATTN_DYN>>>(
        qhi, khi, vhi, mask, ahi);

    // Wo projection + residual
    gemm_hmma<<<dim3(D_ / GN, M_TOT / GM, 1), 256, GEMM_DYN>>>(
        ahi, wthi + 3*DD, bo, bo, bo, prp,
        nullptr, nullptr, nullptr, hidden, x);

    lnorm<<<M_TOT, 256>>>(x, lns, lnb, out);
}